// round 2
// baseline (speedup 1.0000x reference)
#include <cuda_runtime.h>
#include <cuda_fp16.h>
#include <cstdint>

#define BB 512
#define THIST 512
#define HENC 256
#define HH 256
#define AA 256
#define TPRED 32
#define NG 1024  // 4*H

// ---------------- device scratch (static only) ----------------
__device__ __half g_ep_h[(size_t)BB * THIST * AA];    // enc_proj fp16, 134MB
__device__ __half g_eo_h[(size_t)BB * THIST * HENC];  // encoder_outputs fp16, 134MB
__device__ float g_Wt_enc[HENC * AA];                 // [a][e]
__device__ float g_Wcat0r[NG * 512];                  // gate-interleaved: row n=4j+g
__device__ float g_Wcat1r[NG * 512];
__device__ float g_wcol0r[NG];
__device__ float g_bias0r[NG];
__device__ float g_bias1r[NG];
__device__ float g_h0[BB * HH], g_h1[BB * HH];
__device__ float g_c0[BB * HH], g_c1[BB * HH];
__device__ float g_dec_in[BB];
__device__ float g_dp[BB * AA];        // dec_proj for current step
__device__ float g_xcat0[BB * 512];    // [ctx | h0_old]
__device__ float g_xcat1[BB * 512];    // [h0_new | h1_old]
__device__ float g_xcatfc[BB * 512];   // [h1_new | ctx]

// ---------------- helpers ----------------
__device__ __forceinline__ float ftanh_fast(float x) {
    float y;
    asm("tanh.approx.f32 %0, %1;" : "=f"(y) : "f"(x));
    return y;
}
__device__ __forceinline__ float sig_precise(float x) { return 1.f / (1.f + expf(-x)); }

// ---------------- init + prep ----------------
__global__ void init_state(const float* __restrict__ eh, const float* __restrict__ ec) {
    int i = blockIdx.x * blockDim.x + threadIdx.x;
    if (i < BB * HH) {
        g_h0[i] = eh[i];
        g_h1[i] = eh[BB * HH + i];
        g_c0[i] = ec[i];
        g_c1[i] = ec[BB * HH + i];
    }
    if (i < BB) g_dec_in[i] = 0.f;
}

__global__ void prep(const float* __restrict__ Wae,
                     const float* __restrict__ Wih0, const float* __restrict__ Whh0,
                     const float* __restrict__ bih0, const float* __restrict__ bhh0,
                     const float* __restrict__ Wih1, const float* __restrict__ Whh1,
                     const float* __restrict__ bih1, const float* __restrict__ bhh1) {
    int i = blockIdx.x * blockDim.x + threadIdx.x;
    if (i < HENC * AA) {
        int a = i / HENC, e = i % HENC;
        g_Wt_enc[i] = Wae[e * AA + a];
    }
    if (i < NG * 512) {
        int n4 = i >> 9, c = i & 511;
        int j = n4 >> 2, g = n4 & 3;
        int n = g * 256 + j;  // original torch row
        g_Wcat0r[i] = (c < 256) ? Wih0[n * 257 + 1 + c] : Whh0[n * 256 + (c - 256)];
        g_Wcat1r[i] = (c < 256) ? Wih1[n * 256 + c] : Whh1[n * 256 + (c - 256)];
    }
    if (i < NG) {
        int j = i >> 2, g = i & 3;
        int n = g * 256 + j;
        g_wcol0r[i] = Wih0[n * 257];
        g_bias0r[i] = bih0[n] + bhh0[n];
        g_bias1r[i] = bih1[n] + bhh1[n];
    }
}

__global__ void eo_to_half(const float* __restrict__ eo) {
    int i = blockIdx.x * blockDim.x + threadIdx.x;  // one per 4 floats
    const float4 v = ((const float4*)eo)[i];
    __half2 h[2];
    h[0] = __floats2half2_rn(v.x, v.y);
    h[1] = __floats2half2_rn(v.z, v.w);
    ((uint2*)g_eo_h)[i] = *(uint2*)h;
}

// ---------------- enc_proj GEMM: C(fp16)[M,256] = A[M,256] * B^T, 128x128 tile ----------------
__global__ __launch_bounds__(256, 2) void encproj_gemm(const float* __restrict__ Aa) {
    __shared__ float As[8][132];
    __shared__ float Bs[8][132];
    const int m0 = blockIdx.y * 128;
    const int n0 = blockIdx.x * 128;
    const int tid = threadIdx.x;
    const int lr = tid >> 1;          // 0..127
    const int lk = (tid & 1) * 4;     // 0 or 4
    const int tx = tid & 15, ty = tid >> 4;
    const float* Ap = Aa + (size_t)(m0 + lr) * 256 + lk;
    const float* Bp = g_Wt_enc + (size_t)(n0 + lr) * 256 + lk;
    float acc[8][8];
#pragma unroll
    for (int i = 0; i < 8; i++)
#pragma unroll
        for (int j = 0; j < 8; j++) acc[i][j] = 0.f;
    for (int kt = 0; kt < 256; kt += 8) {
        float4 av = *(const float4*)(Ap + kt);
        float4 bv = *(const float4*)(Bp + kt);
        __syncthreads();
        As[lk + 0][lr] = av.x; As[lk + 1][lr] = av.y;
        As[lk + 2][lr] = av.z; As[lk + 3][lr] = av.w;
        Bs[lk + 0][lr] = bv.x; Bs[lk + 1][lr] = bv.y;
        Bs[lk + 2][lr] = bv.z; Bs[lk + 3][lr] = bv.w;
        __syncthreads();
#pragma unroll
        for (int kk = 0; kk < 8; kk++) {
            float ar[8], br[8];
            *(float4*)(ar + 0) = *(const float4*)&As[kk][ty * 8 + 0];
            *(float4*)(ar + 4) = *(const float4*)&As[kk][ty * 8 + 4];
            *(float4*)(br + 0) = *(const float4*)&Bs[kk][tx * 8 + 0];
            *(float4*)(br + 4) = *(const float4*)&Bs[kk][tx * 8 + 4];
#pragma unroll
            for (int i = 0; i < 8; i++)
#pragma unroll
                for (int j = 0; j < 8; j++) acc[i][j] = fmaf(ar[i], br[j], acc[i][j]);
        }
    }
#pragma unroll
    for (int i = 0; i < 8; i++) {
        int m = m0 + ty * 8 + i;
        __half2 hv[4];
#pragma unroll
        for (int q = 0; q < 4; q++) hv[q] = __floats2half2_rn(acc[i][2 * q], acc[i][2 * q + 1]);
        *reinterpret_cast<uint4*>(&g_ep_h[(size_t)m * AA + n0 + tx * 8]) = *reinterpret_cast<uint4*>(hv);
    }
}

// ---------------- fused attention (per step) ----------------
__global__ __launch_bounds__(256) void attn_step(const float* __restrict__ v,
                                                 float* __restrict__ attn_out) {
    __shared__ float s_dp[256];
    __shared__ float s_v[256];
    __shared__ float s_sc[512];
    __shared__ float s_red[8];
    __shared__ float2 s_cp[2][128];
    const int b = blockIdx.x;
    const int tid = threadIdx.x;
    const int lane = tid & 31, w = tid >> 5;

    s_dp[tid] = g_dp[b * 256 + tid];
    s_v[tid] = v[tid];
    __syncthreads();

    float vr[8], dr[8];
#pragma unroll
    for (int i = 0; i < 8; i++) {
        vr[i] = s_v[lane * 8 + i];
        dr[i] = s_dp[lane * 8 + i];
    }

    const __half* ep = g_ep_h + (size_t)b * THIST * AA;
    for (int t = w; t < THIST; t += 8) {
        int4 raw = *(const int4*)(ep + (size_t)t * AA + lane * 8);
        const __half2* hp = (const __half2*)&raw;
        float sum = 0.f;
#pragma unroll
        for (int q = 0; q < 4; q++) {
            float2 f = __half22float2(hp[q]);
            sum = fmaf(vr[2 * q + 0], ftanh_fast(f.x + dr[2 * q + 0]), sum);
            sum = fmaf(vr[2 * q + 1], ftanh_fast(f.y + dr[2 * q + 1]), sum);
        }
#pragma unroll
        for (int off = 16; off; off >>= 1) sum += __shfl_xor_sync(0xffffffffu, sum, off);
        if (lane == 0) s_sc[t] = sum;
    }
    __syncthreads();

    // softmax over 512 scores
    float m = fmaxf(s_sc[tid], s_sc[tid + 256]);
#pragma unroll
    for (int off = 16; off; off >>= 1) m = fmaxf(m, __shfl_xor_sync(0xffffffffu, m, off));
    if (lane == 0) s_red[w] = m;
    __syncthreads();
    float mm = s_red[0];
#pragma unroll
    for (int i = 1; i < 8; i++) mm = fmaxf(mm, s_red[i]);
    float e0 = __expf(s_sc[tid] - mm);
    float e1 = __expf(s_sc[tid + 256] - mm);
    float sm = e0 + e1;
#pragma unroll
    for (int off = 16; off; off >>= 1) sm += __shfl_xor_sync(0xffffffffu, sm, off);
    __syncthreads();
    if (lane == 0) s_red[w] = sm;
    __syncthreads();
    float tot = s_red[0];
#pragma unroll
    for (int i = 1; i < 8; i++) tot += s_red[i];
    float inv = 1.f / tot;
    float p0 = e0 * inv, p1 = e1 * inv;
    s_sc[tid] = p0;
    s_sc[tid + 256] = p1;
    attn_out[(size_t)b * THIST + tid] = p0;
    attn_out[(size_t)b * THIST + tid + 256] = p1;
    __syncthreads();

    // ctx: thread covers e-pair (e2*2, e2*2+1), half the t-range each
    const int e2 = tid & 127;
    const int tpar = tid >> 7;
    const __half2* eoh2 = (const __half2*)(g_eo_h + (size_t)b * THIST * HENC);
    float cx = 0.f, cy = 0.f;
#pragma unroll 4
    for (int t = tpar; t < THIST; t += 2) {
        float2 f = __half22float2(eoh2[(size_t)t * 128 + e2]);
        float p = s_sc[t];
        cx = fmaf(p, f.x, cx);
        cy = fmaf(p, f.y, cy);
    }
    s_cp[tpar][e2] = make_float2(cx, cy);
    __syncthreads();

    const int e = tid;
    const int ee2 = e >> 1;
    float cacc = (e & 1) ? (s_cp[0][ee2].y + s_cp[1][ee2].y)
                         : (s_cp[0][ee2].x + s_cp[1][ee2].x);
    g_xcat0[b * 512 + e] = cacc;                       // ctx
    g_xcat0[b * 512 + 256 + e] = g_h0[b * 256 + e];    // h0_old (for lstm0)
    g_xcat1[b * 512 + 256 + e] = g_h1[b * 256 + e];    // h1_old (for lstm1)
    g_xcatfc[b * 512 + 256 + e] = cacc;                // ctx (for fc)
}

// ---------------- fused LSTM GEMM + cell (gate-interleaved weights) ----------------
template <int CELL>
__global__ __launch_bounds__(256) void lstm_gemm(const float* __restrict__ Aa,
                                                 const float* __restrict__ Bb) {
    __shared__ float As[16][68];
    __shared__ float Bs[16][68];
    const int m0 = blockIdx.y * 64;
    const int n0 = blockIdx.x * 64;
    const int tid = threadIdx.x;
    const int lr = tid >> 2;
    const int lc = (tid & 3) * 4;
    const int tx = tid & 15, ty = tid >> 4;
    const float* Ap = Aa + (size_t)(m0 + lr) * 512 + lc;
    const float* Bp = Bb + (size_t)(n0 + lr) * 512 + lc;
    float acc[4][4];
#pragma unroll
    for (int i = 0; i < 4; i++)
#pragma unroll
        for (int j = 0; j < 4; j++) acc[i][j] = 0.f;
    for (int kt = 0; kt < 512; kt += 16) {
        float4 av = *(const float4*)(Ap + kt);
        float4 bv = *(const float4*)(Bp + kt);
        __syncthreads();
        As[lc + 0][lr] = av.x; As[lc + 1][lr] = av.y;
        As[lc + 2][lr] = av.z; As[lc + 3][lr] = av.w;
        Bs[lc + 0][lr] = bv.x; Bs[lc + 1][lr] = bv.y;
        Bs[lc + 2][lr] = bv.z; Bs[lc + 3][lr] = bv.w;
        __syncthreads();
#pragma unroll
        for (int kk = 0; kk < 16; kk++) {
            float ar[4], br[4];
#pragma unroll
            for (int i = 0; i < 4; i++) ar[i] = As[kk][ty * 4 + i];
#pragma unroll
            for (int j = 0; j < 4; j++) br[j] = Bs[kk][tx * 4 + j];
#pragma unroll
            for (int i = 0; i < 4; i++)
#pragma unroll
                for (int j = 0; j < 4; j++) acc[i][j] = fmaf(ar[i], br[j], acc[i][j]);
        }
    }
    // epilogue: thread's 4 n-values are gates (i,f,g,o) of j
    const int j = (n0 >> 2) + tx;
#pragma unroll
    for (int i = 0; i < 4; i++) {
        const int b = m0 + ty * 4 + i;
        const int idx = b * 256 + j;
        float gi, gf, gg, go;
        if (CELL == 0) {
            const float din = g_dec_in[b];
            gi = acc[i][0] + din * g_wcol0r[4 * j + 0] + g_bias0r[4 * j + 0];
            gf = acc[i][1] + din * g_wcol0r[4 * j + 1] + g_bias0r[4 * j + 1];
            gg = acc[i][2] + din * g_wcol0r[4 * j + 2] + g_bias0r[4 * j + 2];
            go = acc[i][3] + din * g_wcol0r[4 * j + 3] + g_bias0r[4 * j + 3];
        } else {
            gi = acc[i][0] + g_bias1r[4 * j + 0];
            gf = acc[i][1] + g_bias1r[4 * j + 1];
            gg = acc[i][2] + g_bias1r[4 * j + 2];
            go = acc[i][3] + g_bias1r[4 * j + 3];
        }
        if (CELL == 0) {
            float c = sig_precise(gf) * g_c0[idx] + sig_precise(gi) * tanhf(gg);
            float h = sig_precise(go) * tanhf(c);
            g_c0[idx] = c;
            g_h0[idx] = h;                  // read by next step's attn
            g_xcat1[b * 512 + j] = h;       // read by lstm1 (next launch)
        } else {
            float c = sig_precise(gf) * g_c1[idx] + sig_precise(gi) * tanhf(gg);
            float h = sig_precise(go) * tanhf(c);
            g_c1[idx] = c;
            g_h1[idx] = h;                  // read by next step's attn
            g_xcatfc[b * 512 + j] = h;      // read by fc (next launch)
        }
    }
}

// ---------------- fused fc1+relu+fc2 (+ next-step dec_proj) ----------------
__global__ __launch_bounds__(256) void fc_step(const float* __restrict__ Wfc1,
                                               const float* __restrict__ bfc1,
                                               const float* __restrict__ Wfc2,
                                               const float* __restrict__ bfc2,
                                               const float* __restrict__ Wad,
                                               float* __restrict__ outs, int s) {
    __shared__ float sA[8][512];
    __shared__ float sR[8][256];
    const int b0 = blockIdx.x * 8;
    const int tid = threadIdx.x;
    // load 8 rows of xcatfc (4096 floats = 1024 float4)
#pragma unroll
    for (int q = 0; q < 4; q++) {
        int f4 = q * 256 + tid;
        int r = f4 >> 7, c = (f4 & 127) * 4;
        *(float4*)&sA[r][c] = *(const float4*)&g_xcatfc[(size_t)(b0 + r) * 512 + c];
    }
    __syncthreads();

    // fc1 row tid for all 8 batch rows
    float val[8];
#pragma unroll
    for (int r = 0; r < 8; r++) val[r] = 0.f;
    const float4* wrow = (const float4*)(Wfc1 + (size_t)tid * 512);
#pragma unroll 4
    for (int k4 = 0; k4 < 128; k4++) {
        float4 wv = wrow[k4];
#pragma unroll
        for (int r = 0; r < 8; r++) {
            const float4 a = *(const float4*)&sA[r][k4 * 4];
            val[r] = fmaf(a.x, wv.x, val[r]);
            val[r] = fmaf(a.y, wv.y, val[r]);
            val[r] = fmaf(a.z, wv.z, val[r]);
            val[r] = fmaf(a.w, wv.w, val[r]);
        }
    }
    const float bb = bfc1[tid];
    const float w2 = Wfc2[tid];
#pragma unroll
    for (int r = 0; r < 8; r++) sR[r][tid] = fmaxf(val[r] + bb, 0.f) * w2;
    __syncthreads();

    // reduce: warp w handles batch row w
    const int w = tid >> 5, lane = tid & 31;
    float sm = 0.f;
#pragma unroll
    for (int q = 0; q < 8; q++) sm += sR[w][lane + q * 32];
#pragma unroll
    for (int off = 16; off; off >>= 1) sm += __shfl_xor_sync(0xffffffffu, sm, off);
    if (lane == 0) {
        float o = sm + bfc2[0];
        outs[(b0 + w) * TPRED + s] = o;
        g_dec_in[b0 + w] = o;
    }

    // next step's dec_proj: dp[b,a] = sum_h h1_new[b,h] * Wad[h,a]... using Wad^T rows
    // Wad is [H, A] row-major (h-major); we need dp[a] = sum_h h1[h]*Wad[h*A+a].
    // Thread a=tid reads column a: strided. Instead use per-thread row of Wad^T precomp?
    // Simpler: thread a accumulates with Wad read as [h][a]: per h, warp reads contiguous.
    float dpa[8];
#pragma unroll
    for (int r = 0; r < 8; r++) dpa[r] = 0.f;
#pragma unroll 4
    for (int h = 0; h < 256; h++) {
        const float wv = Wad[(size_t)h * AA + tid];  // coalesced across threads
#pragma unroll
        for (int r = 0; r < 8; r++) dpa[r] = fmaf(sA[r][h], wv, dpa[r]);
    }
#pragma unroll
    for (int r = 0; r < 8; r++) g_dp[(b0 + r) * 256 + tid] = dpa[r];
}

// ---------------- initial dec_proj from encoder_hidden[1] ----------------
__global__ __launch_bounds__(256) void dp_init(const float* __restrict__ Wad) {
    __shared__ float sA[8][256];
    const int b0 = blockIdx.x * 8;
    const int tid = threadIdx.x;
#pragma unroll
    for (int q = 0; q < 2; q++) {
        int f4 = q * 256 + tid;
        int r = f4 >> 6, c = (f4 & 63) * 4;
        *(float4*)&sA[r][c] = *(const float4*)&g_h1[(size_t)(b0 + r) * 256 + c];
    }
    __syncthreads();
    float dpa[8];
#pragma unroll
    for (int r = 0; r < 8; r++) dpa[r] = 0.f;
#pragma unroll 4
    for (int h = 0; h < 256; h++) {
        const float wv = Wad[(size_t)h * AA + tid];
#pragma unroll
        for (int r = 0; r < 8; r++) dpa[r] = fmaf(sA[r][h], wv, dpa[r]);
    }
#pragma unroll
    for (int r = 0; r < 8; r++) g_dp[(b0 + r) * 256 + tid] = dpa[r];
}

// ---------------- host launcher ----------------
extern "C" void kernel_launch(void* const* d_in, const int* in_sizes, int n_in,
                              void* d_out, int out_size) {
    int off = (in_sizes[0] == 1) ? 1 : 0;
    const float* enc_out = (const float*)d_in[off + 0];
    const float* enc_h = (const float*)d_in[off + 1];
    const float* enc_c = (const float*)d_in[off + 2];
    const float* Wae = (const float*)d_in[off + 3];
    const float* Wad = (const float*)d_in[off + 4];
    const float* v = (const float*)d_in[off + 5];
    const float* Wih0 = (const float*)d_in[off + 6];
    const float* Whh0 = (const float*)d_in[off + 7];
    const float* bih0 = (const float*)d_in[off + 8];
    const float* bhh0 = (const float*)d_in[off + 9];
    const float* Wih1 = (const float*)d_in[off + 10];
    const float* Whh1 = (const float*)d_in[off + 11];
    const float* bih1 = (const float*)d_in[off + 12];
    const float* bhh1 = (const float*)d_in[off + 13];
    const float* Wfc1 = (const float*)d_in[off + 14];
    const float* bfc1 = (const float*)d_in[off + 15];
    const float* Wfc2 = (const float*)d_in[off + 16];
    const float* bfc2 = (const float*)d_in[off + 17];

    float* out = (float*)d_out;
    float* attn_base = out + (size_t)BB * TPRED;

    float *p_Wcat0r, *p_Wcat1r, *p_xcat0, *p_xcat1;
    cudaGetSymbolAddress((void**)&p_Wcat0r, g_Wcat0r);
    cudaGetSymbolAddress((void**)&p_Wcat1r, g_Wcat1r);
    cudaGetSymbolAddress((void**)&p_xcat0, g_xcat0);
    cudaGetSymbolAddress((void**)&p_xcat1, g_xcat1);

    init_state<<<(BB * HH + 255) / 256, 256>>>(enc_h, enc_c);
    prep<<<2048, 256>>>(Wae, Wih0, Whh0, bih0, bhh0, Wih1, Whh1, bih1, bhh1);
    eo_to_half<<<(BB * THIST * HENC / 4) / 256, 256>>>(enc_out);
    encproj_gemm<<<dim3(2, 2048), 256>>>(enc_out);
    dp_init<<<BB / 8, 256>>>(Wad);

    for (int s = 0; s < TPRED; s++) {
        attn_step<<<BB, 256>>>(v, attn_base + (size_t)s * BB * THIST);
        lstm_gemm<0><<<dim3(16, 8), 256>>>(p_xcat0, p_Wcat0r);
        lstm_gemm<1><<<dim3(16, 8), 256>>>(p_xcat1, p_Wcat1r);
        fc_step<<<BB / 8, 256>>>(Wfc1, bfc1, Wfc2, bfc2, Wad, out, s);
    }
    (void)n_in;
    (void)out_size;
}

// round 4
// speedup vs baseline: 1.4975x; 1.4975x over previous
#include <cuda_runtime.h>
#include <cuda_fp16.h>
#include <cstdint>

#define BB 512
#define THIST 512
#define HENC 256
#define HH 256
#define AA 256
#define TPRED 32
#define NG 1024
#define NCTAS 128

// ---------------- device scratch (static only) ----------------
__device__ __half g_ep_h[(size_t)BB * THIST * AA];    // enc_proj fp16
__device__ __half g_eo_h[(size_t)BB * THIST * HENC];  // encoder_outputs fp16
__device__ float g_Wt_enc[HENC * AA];                 // [a][e] fp32 for encproj
__device__ __half g_Wcat0h[NG * 512];                 // [n][{W_ih0[:,1:]|W_hh0}] fp16
__device__ __half g_Wcat1h[NG * 512];
__device__ __half g_Wfc1h[HH * 512];
__device__ __half g_Wt_dech[AA * HH];                 // [a][h] fp16
__device__ float g_wcol0[NG];
__device__ float g_bias0[NG];
__device__ float g_bias1[NG];
__device__ float g_h0[BB * HH], g_h1[BB * HH];
__device__ float g_c0[BB * HH], g_c1[BB * HH];
__device__ float g_dec_in[BB];
__device__ float g_dp[BB * AA];
__device__ float g_gates[BB * NG];
__device__ float g_fcp[BB * HH];
__device__ __half g_xcat0h[BB * 512];   // [ctx | h0_old]
__device__ __half g_xcat1h[BB * 512];   // [h0_new | h1_old]
__device__ __half g_xcatfch[BB * 512];  // [h1_new | ctx]

// grid barrier state
__device__ unsigned g_count = 0;
__device__ unsigned g_sense = 0;

// ---------------- helpers ----------------
__device__ __forceinline__ float ftanh_fast(float x) {
    float y;
    asm("tanh.approx.f32 %0, %1;" : "=f"(y) : "f"(x));
    return y;
}
__device__ __forceinline__ float sig_precise(float x) { return 1.f / (1.f + expf(-x)); }

__device__ __forceinline__ uint32_t smem_u32(const void* p) {
    uint32_t a;
    asm("{.reg .u64 t; cvta.to.shared.u64 t, %1; cvt.u32.u64 %0, t;}" : "=r"(a) : "l"(p));
    return a;
}
__device__ __forceinline__ void ldsm_x4(uint32_t addr, uint32_t& r0, uint32_t& r1,
                                        uint32_t& r2, uint32_t& r3) {
    asm volatile("ldmatrix.sync.aligned.m8n8.x4.shared.b16 {%0,%1,%2,%3}, [%4];"
                 : "=r"(r0), "=r"(r1), "=r"(r2), "=r"(r3) : "r"(addr));
}
// NON-transposed x2: B stored [n][k] row-major == (k x n) col-major, which is
// exactly what mma .col wants; non-trans ldmatrix delivers (n=lane/4, k=2*(lane%4)+h).
__device__ __forceinline__ void ldsm_x2(uint32_t addr, uint32_t& r0, uint32_t& r1) {
    asm volatile("ldmatrix.sync.aligned.m8n8.x2.shared.b16 {%0,%1}, [%2];"
                 : "=r"(r0), "=r"(r1) : "r"(addr));
}
__device__ __forceinline__ void mma16816(float* d, uint32_t a0, uint32_t a1, uint32_t a2,
                                         uint32_t a3, uint32_t b0, uint32_t b1) {
    asm volatile(
        "mma.sync.aligned.m16n8k16.row.col.f32.f16.f16.f32 "
        "{%0,%1,%2,%3},{%4,%5,%6,%7},{%8,%9},{%0,%1,%2,%3};"
        : "+f"(d[0]), "+f"(d[1]), "+f"(d[2]), "+f"(d[3])
        : "r"(a0), "r"(a1), "r"(a2), "r"(a3), "r"(b0), "r"(b1));
}

__device__ __forceinline__ void grid_barrier(unsigned* eps) {
    __syncthreads();
    if (threadIdx.x == 0) {
        unsigned target = ++(*eps);
        __threadfence();
        unsigned old = atomicAdd(&g_count, 1);
        if (old == NCTAS - 1) {
            g_count = 0;
            __threadfence();
            atomicExch(&g_sense, target);
        } else {
            while (atomicAdd(&g_sense, 0) != target) __nanosleep(64);
        }
    }
    __syncthreads();
}

// ---------------- init + prep ----------------
__global__ void init_state(const float* __restrict__ eh, const float* __restrict__ ec) {
    int i = blockIdx.x * blockDim.x + threadIdx.x;
    if (i < BB * HH) {
        g_h0[i] = eh[i];
        g_h1[i] = eh[BB * HH + i];
        g_c0[i] = ec[i];
        g_c1[i] = ec[BB * HH + i];
    }
    if (i < BB) g_dec_in[i] = 0.f;
}

__global__ void prep(const float* __restrict__ Wae, const float* __restrict__ Wad,
                     const float* __restrict__ Wih0, const float* __restrict__ Whh0,
                     const float* __restrict__ bih0, const float* __restrict__ bhh0,
                     const float* __restrict__ Wih1, const float* __restrict__ Whh1,
                     const float* __restrict__ bih1, const float* __restrict__ bhh1,
                     const float* __restrict__ Wfc1) {
    int i = blockIdx.x * blockDim.x + threadIdx.x;
    if (i < HENC * AA) {
        int a = i / HENC, e = i % HENC;
        g_Wt_enc[i] = Wae[e * AA + a];
    }
    if (i < NG * 512) {
        int n = i >> 9, c = i & 511;
        g_Wcat0h[i] = __float2half((c < 256) ? Wih0[n * 257 + 1 + c] : Whh0[n * 256 + (c - 256)]);
        g_Wcat1h[i] = __float2half((c < 256) ? Wih1[n * 256 + c] : Whh1[n * 256 + (c - 256)]);
    }
    if (i < HH * 512) g_Wfc1h[i] = __float2half(Wfc1[i]);
    if (i < AA * HH) {
        int a = i >> 8, h = i & 255;
        g_Wt_dech[i] = __float2half(Wad[h * AA + a]);
    }
    if (i < NG) {
        g_wcol0[i] = Wih0[i * 257];
        g_bias0[i] = bih0[i] + bhh0[i];
        g_bias1[i] = bih1[i] + bhh1[i];
    }
}

__global__ void eo_to_half(const float* __restrict__ eo) {
    int i = blockIdx.x * blockDim.x + threadIdx.x;
    const float4 v = ((const float4*)eo)[i];
    __half2 h[2];
    h[0] = __floats2half2_rn(v.x, v.y);
    h[1] = __floats2half2_rn(v.z, v.w);
    ((uint2*)g_eo_h)[i] = *(uint2*)h;
}

// ---------------- enc_proj GEMM (fp32 FFMA, 128x128, fp16 out) ----------------
__global__ __launch_bounds__(256, 2) void encproj_gemm(const float* __restrict__ Aa) {
    __shared__ float As[8][132];
    __shared__ float Bs[8][132];
    const int m0 = blockIdx.y * 128;
    const int n0 = blockIdx.x * 128;
    const int tid = threadIdx.x;
    const int lr = tid >> 1;
    const int lk = (tid & 1) * 4;
    const int tx = tid & 15, ty = tid >> 4;
    const float* Ap = Aa + (size_t)(m0 + lr) * 256 + lk;
    const float* Bp = g_Wt_enc + (size_t)(n0 + lr) * 256 + lk;
    float acc[8][8];
#pragma unroll
    for (int i = 0; i < 8; i++)
#pragma unroll
        for (int j = 0; j < 8; j++) acc[i][j] = 0.f;
    for (int kt = 0; kt < 256; kt += 8) {
        float4 av = *(const float4*)(Ap + kt);
        float4 bv = *(const float4*)(Bp + kt);
        __syncthreads();
        As[lk + 0][lr] = av.x; As[lk + 1][lr] = av.y;
        As[lk + 2][lr] = av.z; As[lk + 3][lr] = av.w;
        Bs[lk + 0][lr] = bv.x; Bs[lk + 1][lr] = bv.y;
        Bs[lk + 2][lr] = bv.z; Bs[lk + 3][lr] = bv.w;
        __syncthreads();
#pragma unroll
        for (int kk = 0; kk < 8; kk++) {
            float ar[8], br[8];
            *(float4*)(ar + 0) = *(const float4*)&As[kk][ty * 8 + 0];
            *(float4*)(ar + 4) = *(const float4*)&As[kk][ty * 8 + 4];
            *(float4*)(br + 0) = *(const float4*)&Bs[kk][tx * 8 + 0];
            *(float4*)(br + 4) = *(const float4*)&Bs[kk][tx * 8 + 4];
#pragma unroll
            for (int i = 0; i < 8; i++)
#pragma unroll
                for (int j = 0; j < 8; j++) acc[i][j] = fmaf(ar[i], br[j], acc[i][j]);
        }
    }
#pragma unroll
    for (int i = 0; i < 8; i++) {
        int m = m0 + ty * 8 + i;
        __half2 hv[4];
#pragma unroll
        for (int q = 0; q < 4; q++) hv[q] = __floats2half2_rn(acc[i][2 * q], acc[i][2 * q + 1]);
        *reinterpret_cast<uint4*>(&g_ep_h[(size_t)m * AA + n0 + tx * 8]) = *reinterpret_cast<uint4*>(hv);
    }
}

// ---------------- fused attention (per step) ----------------
__global__ __launch_bounds__(256) void attn_step(const float* __restrict__ v,
                                                 float* __restrict__ attn_out) {
    __shared__ float s_dp[256];
    __shared__ float s_v[256];
    __shared__ float s_sc[512];
    __shared__ float s_red[8];
    __shared__ float2 s_cp[2][128];
    const int b = blockIdx.x;
    const int tid = threadIdx.x;
    const int lane = tid & 31, w = tid >> 5;

    s_dp[tid] = g_dp[b * 256 + tid];
    s_v[tid] = v[tid];
    __syncthreads();

    float vr[8], dr[8];
#pragma unroll
    for (int i = 0; i < 8; i++) {
        vr[i] = s_v[lane * 8 + i];
        dr[i] = s_dp[lane * 8 + i];
    }

    const __half* ep = g_ep_h + (size_t)b * THIST * AA;
    for (int t = w * 2; t < THIST; t += 16) {
        int4 raw0 = *(const int4*)(ep + (size_t)t * AA + lane * 8);
        int4 raw1 = *(const int4*)(ep + (size_t)(t + 1) * AA + lane * 8);
        const __half2* h0p = (const __half2*)&raw0;
        const __half2* h1p = (const __half2*)&raw1;
        float s0 = 0.f, s1 = 0.f;
#pragma unroll
        for (int q = 0; q < 4; q++) {
            float2 f0 = __half22float2(h0p[q]);
            float2 f1 = __half22float2(h1p[q]);
            s0 = fmaf(vr[2 * q + 0], ftanh_fast(f0.x + dr[2 * q + 0]), s0);
            s0 = fmaf(vr[2 * q + 1], ftanh_fast(f0.y + dr[2 * q + 1]), s0);
            s1 = fmaf(vr[2 * q + 0], ftanh_fast(f1.x + dr[2 * q + 0]), s1);
            s1 = fmaf(vr[2 * q + 1], ftanh_fast(f1.y + dr[2 * q + 1]), s1);
        }
#pragma unroll
        for (int off = 16; off; off >>= 1) {
            s0 += __shfl_xor_sync(0xffffffffu, s0, off);
            s1 += __shfl_xor_sync(0xffffffffu, s1, off);
        }
        if (lane == 0) {
            s_sc[t] = s0;
            s_sc[t + 1] = s1;
        }
    }
    __syncthreads();

    float m = fmaxf(s_sc[tid], s_sc[tid + 256]);
#pragma unroll
    for (int off = 16; off; off >>= 1) m = fmaxf(m, __shfl_xor_sync(0xffffffffu, m, off));
    if (lane == 0) s_red[w] = m;
    __syncthreads();
    float mm = s_red[0];
#pragma unroll
    for (int i = 1; i < 8; i++) mm = fmaxf(mm, s_red[i]);
    float e0 = __expf(s_sc[tid] - mm);
    float e1 = __expf(s_sc[tid + 256] - mm);
    float sm = e0 + e1;
#pragma unroll
    for (int off = 16; off; off >>= 1) sm += __shfl_xor_sync(0xffffffffu, sm, off);
    __syncthreads();
    if (lane == 0) s_red[w] = sm;
    __syncthreads();
    float tot = s_red[0];
#pragma unroll
    for (int i = 1; i < 8; i++) tot += s_red[i];
    float inv = 1.f / tot;
    float p0 = e0 * inv, p1 = e1 * inv;
    s_sc[tid] = p0;
    s_sc[tid + 256] = p1;
    attn_out[(size_t)b * THIST + tid] = p0;
    attn_out[(size_t)b * THIST + tid + 256] = p1;
    __syncthreads();

    const int e2 = tid & 127;
    const int tpar = tid >> 7;
    const __half2* eoh2 = (const __half2*)(g_eo_h + (size_t)b * THIST * HENC);
    float cx = 0.f, cy = 0.f;
#pragma unroll 4
    for (int t = tpar; t < THIST; t += 2) {
        float2 f = __half22float2(eoh2[(size_t)t * 128 + e2]);
        float p = s_sc[t];
        cx = fmaf(p, f.x, cx);
        cy = fmaf(p, f.y, cy);
    }
    s_cp[tpar][e2] = make_float2(cx, cy);
    __syncthreads();

    const int e = tid;
    const int ee2 = e >> 1;
    float cacc = (e & 1) ? (s_cp[0][ee2].y + s_cp[1][ee2].y)
                         : (s_cp[0][ee2].x + s_cp[1][ee2].x);
    g_xcat0h[b * 512 + e] = __float2half(cacc);
    g_xcat0h[b * 512 + 256 + e] = __float2half(g_h0[b * 256 + e]);
    g_xcatfch[b * 512 + 256 + e] = __float2half(cacc);
}

// ---------------- fp16 MMA 64x64 tile GEMM core ----------------
__device__ void gemm_mma_64x64(const __half* __restrict__ A, int lda,
                               const __half* __restrict__ B, int ldb,
                               int m0, int n0, int ktot, float cf[2][2][4]) {
    static __shared__ __half sA[64 * 40];
    static __shared__ __half sB[64 * 40];
    const int tid = threadIdx.x, lane = tid & 31, wid = tid >> 5;
    const int wm = wid & 1, wn = wid >> 1;
#pragma unroll
    for (int mt = 0; mt < 2; mt++)
#pragma unroll
        for (int nt = 0; nt < 2; nt++)
#pragma unroll
            for (int q = 0; q < 4; q++) cf[mt][nt][q] = 0.f;
    const int lrow = tid >> 2, lcol = (tid & 3) * 8;
    const uint32_t aBase = smem_u32(sA), bBase = smem_u32(sB);
    const int arow = wm * 32 + (lane & 15);
    const int acol8 = 8 * (lane >> 4);
    const int brow = wn * 16 + (lane & 7);
    const int bcol8 = 8 * ((lane >> 3) & 1);

    for (int kc = 0; kc < ktot; kc += 32) {
        __syncthreads();
        *(uint4*)&sA[lrow * 40 + lcol] = *(const uint4*)&A[(size_t)(m0 + lrow) * lda + kc + lcol];
        *(uint4*)&sB[lrow * 40 + lcol] = *(const uint4*)&B[(size_t)(n0 + lrow) * ldb + kc + lcol];
        __syncthreads();
#pragma unroll
        for (int ks = 0; ks < 32; ks += 16) {
            uint32_t a[2][4], bfrag[2][2];
#pragma unroll
            for (int mt = 0; mt < 2; mt++) {
                ldsm_x4(aBase + ((arow + mt * 16) * 40 + ks + acol8) * 2,
                        a[mt][0], a[mt][1], a[mt][2], a[mt][3]);
            }
#pragma unroll
            for (int nt = 0; nt < 2; nt++) {
                ldsm_x2(bBase + ((brow + nt * 8) * 40 + ks + bcol8) * 2,
                        bfrag[nt][0], bfrag[nt][1]);
            }
#pragma unroll
            for (int mt = 0; mt < 2; mt++)
#pragma unroll
                for (int nt = 0; nt < 2; nt++)
                    mma16816(cf[mt][nt], a[mt][0], a[mt][1], a[mt][2], a[mt][3],
                             bfrag[nt][0], bfrag[nt][1]);
        }
    }
}

// ---------------- fused recurrent step ----------------
__global__ __launch_bounds__(256) void recurrent_step(const float* __restrict__ bfc1,
                                                      const float* __restrict__ Wfc2,
                                                      const float* __restrict__ bfc2,
                                                      float* __restrict__ outs, int s) {
    unsigned eps = 0;
    if (threadIdx.x == 0) eps = atomicAdd(&g_sense, 0);
    const int cta = blockIdx.x;
    const int tid = threadIdx.x;
    const int lane = tid & 31, wid = tid >> 5;
    const int wm = wid & 1, wn = wid >> 1;
    const int erow = wm * 32 + (lane >> 2);
    const int ecol = wn * 16 + (lane & 3) * 2;
    float cf[2][2][4];

    // --- P0: lstm0 gates ---
    {
        const int m0 = (cta & 7) * 64, n0 = (cta >> 3) * 64;
        gemm_mma_64x64(g_xcat0h, 512, g_Wcat0h, 512, m0, n0, 512, cf);
#pragma unroll
        for (int mt = 0; mt < 2; mt++)
#pragma unroll
            for (int nt = 0; nt < 2; nt++) {
                int r = m0 + erow + mt * 16, c = n0 + ecol + nt * 8;
                *(float2*)&g_gates[(size_t)r * NG + c] = make_float2(cf[mt][nt][0], cf[mt][nt][1]);
                *(float2*)&g_gates[(size_t)(r + 8) * NG + c] = make_float2(cf[mt][nt][2], cf[mt][nt][3]);
            }
    }
    grid_barrier(&eps);

    // --- P1: cell0 ---
#pragma unroll
    for (int q = 0; q < 4; q++) {
        int idx = cta * 1024 + q * 256 + tid;
        int b = idx >> 8, j = idx & 255;
        float din = g_dec_in[b];
        const float* gb = g_gates + (size_t)b * NG;
        float gi = __ldcg(gb + j) + din * g_wcol0[j] + g_bias0[j];
        float gf = __ldcg(gb + 256 + j) + din * g_wcol0[256 + j] + g_bias0[256 + j];
        float gg = __ldcg(gb + 512 + j) + din * g_wcol0[512 + j] + g_bias0[512 + j];
        float go = __ldcg(gb + 768 + j) + din * g_wcol0[768 + j] + g_bias0[768 + j];
        float c = sig_precise(gf) * g_c0[idx] + sig_precise(gi) * tanhf(gg);
        float h = sig_precise(go) * tanhf(c);
        g_c0[idx] = c;
        g_h0[idx] = h;
        g_xcat1h[b * 512 + j] = __float2half(h);
        g_xcat1h[b * 512 + 256 + j] = __float2half(g_h1[idx]);
    }
    grid_barrier(&eps);

    // --- P2: lstm1 gates ---
    {
        const int m0 = (cta & 7) * 64, n0 = (cta >> 3) * 64;
        gemm_mma_64x64(g_xcat1h, 512, g_Wcat1h, 512, m0, n0, 512, cf);
#pragma unroll
        for (int mt = 0; mt < 2; mt++)
#pragma unroll
            for (int nt = 0; nt < 2; nt++) {
                int r = m0 + erow + mt * 16, c = n0 + ecol + nt * 8;
                *(float2*)&g_gates[(size_t)r * NG + c] = make_float2(cf[mt][nt][0], cf[mt][nt][1]);
                *(float2*)&g_gates[(size_t)(r + 8) * NG + c] = make_float2(cf[mt][nt][2], cf[mt][nt][3]);
            }
    }
    grid_barrier(&eps);

    // --- P3: cell1 ---
#pragma unroll
    for (int q = 0; q < 4; q++) {
        int idx = cta * 1024 + q * 256 + tid;
        int b = idx >> 8, j = idx & 255;
        const float* gb = g_gates + (size_t)b * NG;
        float gi = __ldcg(gb + j) + g_bias1[j];
        float gf = __ldcg(gb + 256 + j) + g_bias1[256 + j];
        float gg = __ldcg(gb + 512 + j) + g_bias1[512 + j];
        float go = __ldcg(gb + 768 + j) + g_bias1[768 + j];
        float c = sig_precise(gf) * g_c1[idx] + sig_precise(gi) * tanhf(gg);
        float h = sig_precise(go) * tanhf(c);
        g_c1[idx] = c;
        g_h1[idx] = h;
        g_xcatfch[b * 512 + j] = __float2half(h);
    }
    grid_barrier(&eps);

    // --- P4: fc1 (ctas 0-31) and dec_proj (ctas 32-63) ---
    if (cta < 32) {
        const int m0 = (cta & 7) * 64, n0 = (cta >> 3) * 64;
        gemm_mma_64x64(g_xcatfch, 512, g_Wfc1h, 512, m0, n0, 512, cf);
#pragma unroll
        for (int mt = 0; mt < 2; mt++)
#pragma unroll
            for (int nt = 0; nt < 2; nt++) {
                int r = m0 + erow + mt * 16, c = n0 + ecol + nt * 8;
                float v0 = fmaxf(cf[mt][nt][0] + bfc1[c], 0.f) * Wfc2[c];
                float v1 = fmaxf(cf[mt][nt][1] + bfc1[c + 1], 0.f) * Wfc2[c + 1];
                float v2 = fmaxf(cf[mt][nt][2] + bfc1[c], 0.f) * Wfc2[c];
                float v3 = fmaxf(cf[mt][nt][3] + bfc1[c + 1], 0.f) * Wfc2[c + 1];
                *(float2*)&g_fcp[(size_t)r * HH + c] = make_float2(v0, v1);
                *(float2*)&g_fcp[(size_t)(r + 8) * HH + c] = make_float2(v2, v3);
            }
    } else if (cta < 64) {
        const int c2 = cta - 32;
        const int m0 = (c2 & 7) * 64, n0 = (c2 >> 3) * 64;
        gemm_mma_64x64(g_xcatfch, 512, g_Wt_dech, 256, m0, n0, 256, cf);
#pragma unroll
        for (int mt = 0; mt < 2; mt++)
#pragma unroll
            for (int nt = 0; nt < 2; nt++) {
                int r = m0 + erow + mt * 16, c = n0 + ecol + nt * 8;
                *(float2*)&g_dp[(size_t)r * AA + c] = make_float2(cf[mt][nt][0], cf[mt][nt][1]);
                *(float2*)&g_dp[(size_t)(r + 8) * AA + c] = make_float2(cf[mt][nt][2], cf[mt][nt][3]);
            }
    }
    grid_barrier(&eps);

    // --- P5: fc2 reduce ---
    {
        __shared__ float sred[8];
        const int b = cta * 4 + (tid >> 6);
        const int l = tid & 63;
        const float* fp = g_fcp + (size_t)b * HH;
        float v = __ldcg(fp + l) + __ldcg(fp + 64 + l) + __ldcg(fp + 128 + l) + __ldcg(fp + 192 + l);
#pragma unroll
        for (int off = 16; off; off >>= 1) v += __shfl_xor_sync(0xffffffffu, v, off);
        if (lane == 0) sred[wid] = v;
        __syncthreads();
        if (tid < 4) {
            float o = sred[2 * tid] + sred[2 * tid + 1] + bfc2[0];
            int b2 = cta * 4 + tid;
            outs[b2 * TPRED + s] = o;
            g_dec_in[b2] = o;
        }
    }
}

// ---------------- initial dec_proj from encoder_hidden[1] ----------------
__global__ __launch_bounds__(256) void dp_init(const float* __restrict__ Wad) {
    __shared__ float sA[8][256];
    const int b0 = blockIdx.x * 8;
    const int tid = threadIdx.x;
#pragma unroll
    for (int q = 0; q < 2; q++) {
        int f4 = q * 256 + tid;
        int r = f4 >> 6, c = (f4 & 63) * 4;
        *(float4*)&sA[r][c] = *(const float4*)&g_h1[(size_t)(b0 + r) * 256 + c];
    }
    __syncthreads();
    float dpa[8];
#pragma unroll
    for (int r = 0; r < 8; r++) dpa[r] = 0.f;
#pragma unroll 4
    for (int h = 0; h < 256; h++) {
        const float wv = Wad[(size_t)h * AA + tid];
#pragma unroll
        for (int r = 0; r < 8; r++) dpa[r] = fmaf(sA[r][h], wv, dpa[r]);
    }
#pragma unroll
    for (int r = 0; r < 8; r++) g_dp[(b0 + r) * 256 + tid] = dpa[r];
}

// ---------------- host launcher ----------------
extern "C" void kernel_launch(void* const* d_in, const int* in_sizes, int n_in,
                              void* d_out, int out_size) {
    int off = (in_sizes[0] == 1) ? 1 : 0;
    const float* enc_out = (const float*)d_in[off + 0];
    const float* enc_h = (const float*)d_in[off + 1];
    const float* enc_c = (const float*)d_in[off + 2];
    const float* Wae = (const float*)d_in[off + 3];
    const float* Wad = (const float*)d_in[off + 4];
    const float* v = (const float*)d_in[off + 5];
    const float* Wih0 = (const float*)d_in[off + 6];
    const float* Whh0 = (const float*)d_in[off + 7];
    const float* bih0 = (const float*)d_in[off + 8];
    const float* bhh0 = (const float*)d_in[off + 9];
    const float* Wih1 = (const float*)d_in[off + 10];
    const float* Whh1 = (const float*)d_in[off + 11];
    const float* bih1 = (const float*)d_in[off + 12];
    const float* bhh1 = (const float*)d_in[off + 13];
    const float* Wfc1 = (const float*)d_in[off + 14];
    const float* bfc1 = (const float*)d_in[off + 15];
    const float* Wfc2 = (const float*)d_in[off + 16];
    const float* bfc2 = (const float*)d_in[off + 17];

    float* out = (float*)d_out;
    float* attn_base = out + (size_t)BB * TPRED;

    init_state<<<(BB * HH + 255) / 256, 256>>>(enc_h, enc_c);
    prep<<<2048, 256>>>(Wae, Wad, Wih0, Whh0, bih0, bhh0, Wih1, Whh1, bih1, bhh1, Wfc1);
    eo_to_half<<<(BB * THIST * HENC / 4) / 256, 256>>>(enc_out);
    encproj_gemm<<<dim3(2, 2048), 256>>>(enc_out);
    dp_init<<<BB / 8, 256>>>(Wad);

    for (int s = 0; s < TPRED; s++) {
        attn_step<<<BB, 256>>>(v, attn_base + (size_t)s * BB * THIST);
        recurrent_step<<<NCTAS, 256>>>(bfc1, Wfc2, bfc2, out, s);
    }
    (void)n_in;
    (void)out_size;
}

// round 5
// speedup vs baseline: 1.6217x; 1.0829x over previous
#include <cuda_runtime.h>
#include <cuda_fp16.h>
#include <cstdint>

#define BB 512
#define THIST 512
#define HENC 256
#define HH 256
#define AA 256
#define TPRED 32
#define NG 1024
#define NCTAS 128

// ---------------- device scratch (static only) ----------------
__device__ __half g_ep_h[(size_t)BB * THIST * AA];    // enc_proj fp16
__device__ __half g_eo_h[(size_t)BB * THIST * HENC];  // encoder_outputs fp16 hi
__device__ __half g_eo_l[(size_t)BB * THIST * HENC];  // fp16 lo residual
__device__ __half g_Wt_ench[HENC * AA];               // [a][e] hi
__device__ __half g_Wt_encl[HENC * AA];               // [a][e] lo
__device__ __half g_Wcat0rh[NG * 512];                // gate-interleaved n'=4j+g
__device__ __half g_Wcat1rh[NG * 512];
__device__ __half g_Wfc1h[HH * 512];
__device__ __half g_Wt_dech[AA * HH];                 // [a][h]
__device__ float g_wcol0r[NG];
__device__ float g_bias0r[NG];
__device__ float g_bias1r[NG];
__device__ float g_h0[BB * HH], g_h1[BB * HH];
__device__ float g_c0[BB * HH], g_c1[BB * HH];
__device__ float g_dec_in[BB];
__device__ float g_dp[BB * AA];
__device__ float g_fcp4[BB * 4];                      // fc partials (4 per batch row)
__device__ __half g_xcat0h[BB * 512];                 // [ctx | h0_old]
__device__ __half g_xcat1h[BB * 512];                 // [h0_new | h1_old]
__device__ __half g_xcatfch[BB * 512];                // [h1_new | ctx]

__device__ unsigned g_count = 0;
__device__ unsigned g_sense = 0;

// ---------------- helpers ----------------
__device__ __forceinline__ float ftanh_fast(float x) {
    float y;
    asm("tanh.approx.f32 %0, %1;" : "=f"(y) : "f"(x));
    return y;
}
__device__ __forceinline__ float sig_precise(float x) { return 1.f / (1.f + expf(-x)); }

__device__ __forceinline__ uint32_t smem_u32(const void* p) {
    uint32_t a;
    asm("{.reg .u64 t; cvta.to.shared.u64 t, %1; cvt.u32.u64 %0, t;}" : "=r"(a) : "l"(p));
    return a;
}
__device__ __forceinline__ void ldsm_x4(uint32_t addr, uint32_t& r0, uint32_t& r1,
                                        uint32_t& r2, uint32_t& r3) {
    asm volatile("ldmatrix.sync.aligned.m8n8.x4.shared.b16 {%0,%1,%2,%3}, [%4];"
                 : "=r"(r0), "=r"(r1), "=r"(r2), "=r"(r3) : "r"(addr));
}
__device__ __forceinline__ void ldsm_x2(uint32_t addr, uint32_t& r0, uint32_t& r1) {
    asm volatile("ldmatrix.sync.aligned.m8n8.x2.shared.b16 {%0,%1}, [%2];"
                 : "=r"(r0), "=r"(r1) : "r"(addr));
}
__device__ __forceinline__ void mma16816(float* d, uint32_t a0, uint32_t a1, uint32_t a2,
                                         uint32_t a3, uint32_t b0, uint32_t b1) {
    asm volatile(
        "mma.sync.aligned.m16n8k16.row.col.f32.f16.f16.f32 "
        "{%0,%1,%2,%3},{%4,%5,%6,%7},{%8,%9},{%0,%1,%2,%3};"
        : "+f"(d[0]), "+f"(d[1]), "+f"(d[2]), "+f"(d[3])
        : "r"(a0), "r"(a1), "r"(a2), "r"(a3), "r"(b0), "r"(b1));
}

__device__ __forceinline__ void grid_barrier(unsigned* eps) {
    __syncthreads();
    if (threadIdx.x == 0) {
        unsigned target = ++(*eps);
        __threadfence();
        unsigned old = atomicAdd(&g_count, 1);
        if (old == NCTAS - 1) {
            g_count = 0;
            __threadfence();
            atomicExch(&g_sense, target);
        } else {
            while (atomicAdd(&g_sense, 0) != target) __nanosleep(64);
        }
    }
    __syncthreads();
}

// ---------------- init + prep ----------------
__global__ void init_state(const float* __restrict__ eh, const float* __restrict__ ec) {
    int i = blockIdx.x * blockDim.x + threadIdx.x;
    if (i < BB * HH) {
        g_h0[i] = eh[i];
        g_h1[i] = eh[BB * HH + i];
        g_c0[i] = ec[i];
        g_c1[i] = ec[BB * HH + i];
    }
    if (i < BB) g_dec_in[i] = 0.f;
}

__global__ void prep(const float* __restrict__ Wae, const float* __restrict__ Wad,
                     const float* __restrict__ Wih0, const float* __restrict__ Whh0,
                     const float* __restrict__ bih0, const float* __restrict__ bhh0,
                     const float* __restrict__ Wih1, const float* __restrict__ Whh1,
                     const float* __restrict__ bih1, const float* __restrict__ bhh1,
                     const float* __restrict__ Wfc1) {
    int i = blockIdx.x * blockDim.x + threadIdx.x;
    if (i < HENC * AA) {
        int a = i / HENC, e = i % HENC;
        float w = Wae[e * AA + a];
        __half hi = __float2half(w);
        g_Wt_ench[i] = hi;
        g_Wt_encl[i] = __float2half(w - __half2float(hi));
    }
    if (i < NG * 512) {
        int n4 = i >> 9, c = i & 511;
        int j = n4 >> 2, g = n4 & 3;
        int n = g * 256 + j;
        g_Wcat0rh[i] = __float2half((c < 256) ? Wih0[n * 257 + 1 + c] : Whh0[n * 256 + (c - 256)]);
        g_Wcat1rh[i] = __float2half((c < 256) ? Wih1[n * 256 + c] : Whh1[n * 256 + (c - 256)]);
    }
    if (i < HH * 512) g_Wfc1h[i] = __float2half(Wfc1[i]);
    if (i < AA * HH) {
        int a = i >> 8, h = i & 255;
        g_Wt_dech[i] = __float2half(Wad[h * AA + a]);
    }
    if (i < NG) {
        int j = i >> 2, g = i & 3;
        int n = g * 256 + j;
        g_wcol0r[i] = Wih0[n * 257];
        g_bias0r[i] = bih0[n] + bhh0[n];
        g_bias1r[i] = bih1[n] + bhh1[n];
    }
}

__global__ void prep_eo(const float* __restrict__ eo) {
    int i = blockIdx.x * blockDim.x + threadIdx.x;  // per 4 floats
    const float4 v = ((const float4*)eo)[i];
    __half h0 = __float2half(v.x), h1 = __float2half(v.y);
    __half h2 = __float2half(v.z), h3 = __float2half(v.w);
    __half2 hhi[2] = {__halves2half2(h0, h1), __halves2half2(h2, h3)};
    __half2 hlo[2] = {
        __floats2half2_rn(v.x - __half2float(h0), v.y - __half2float(h1)),
        __floats2half2_rn(v.z - __half2float(h2), v.w - __half2float(h3))};
    ((uint2*)g_eo_h)[i] = *(uint2*)hhi;
    ((uint2*)g_eo_l)[i] = *(uint2*)hlo;
}

// ---------------- enc_proj via tensor cores, hi/lo split (3 MMA) ----------------
__global__ __launch_bounds__(256) void encproj_mma() {
    __shared__ __half sAh[64 * 40], sAl[64 * 40];
    __shared__ __half sBh[64 * 40], sBl[64 * 40];
    const int m0 = blockIdx.y * 64;
    const int n0 = blockIdx.x * 64;
    const int tid = threadIdx.x, lane = tid & 31, wid = tid >> 5;
    const int wm = wid & 1, wn = wid >> 1;
    float cf[2][2][4];
#pragma unroll
    for (int mt = 0; mt < 2; mt++)
#pragma unroll
        for (int nt = 0; nt < 2; nt++)
#pragma unroll
            for (int q = 0; q < 4; q++) cf[mt][nt][q] = 0.f;
    const int lrow = tid >> 2, lcol = (tid & 3) * 8;
    const uint32_t ahB = smem_u32(sAh), alB = smem_u32(sAl);
    const uint32_t bhB = smem_u32(sBh), blB = smem_u32(sBl);
    const int arow = wm * 32 + (lane & 15);
    const int acol8 = 8 * (lane >> 4);
    const int brow = wn * 16 + (lane & 7);
    const int bcol8 = 8 * ((lane >> 3) & 1);

    for (int kc = 0; kc < 256; kc += 32) {
        __syncthreads();
        *(uint4*)&sAh[lrow * 40 + lcol] = *(const uint4*)&g_eo_h[(size_t)(m0 + lrow) * 256 + kc + lcol];
        *(uint4*)&sAl[lrow * 40 + lcol] = *(const uint4*)&g_eo_l[(size_t)(m0 + lrow) * 256 + kc + lcol];
        *(uint4*)&sBh[lrow * 40 + lcol] = *(const uint4*)&g_Wt_ench[(size_t)(n0 + lrow) * 256 + kc + lcol];
        *(uint4*)&sBl[lrow * 40 + lcol] = *(const uint4*)&g_Wt_encl[(size_t)(n0 + lrow) * 256 + kc + lcol];
        __syncthreads();
#pragma unroll
        for (int ks = 0; ks < 32; ks += 16) {
            uint32_t ah[2][4], al[2][4], bh[2][2], bl[2][2];
#pragma unroll
            for (int mt = 0; mt < 2; mt++) {
                ldsm_x4(ahB + ((arow + mt * 16) * 40 + ks + acol8) * 2,
                        ah[mt][0], ah[mt][1], ah[mt][2], ah[mt][3]);
                ldsm_x4(alB + ((arow + mt * 16) * 40 + ks + acol8) * 2,
                        al[mt][0], al[mt][1], al[mt][2], al[mt][3]);
            }
#pragma unroll
            for (int nt = 0; nt < 2; nt++) {
                ldsm_x2(bhB + ((brow + nt * 8) * 40 + ks + bcol8) * 2, bh[nt][0], bh[nt][1]);
                ldsm_x2(blB + ((brow + nt * 8) * 40 + ks + bcol8) * 2, bl[nt][0], bl[nt][1]);
            }
#pragma unroll
            for (int mt = 0; mt < 2; mt++)
#pragma unroll
                for (int nt = 0; nt < 2; nt++) {
                    mma16816(cf[mt][nt], ah[mt][0], ah[mt][1], ah[mt][2], ah[mt][3],
                             bh[nt][0], bh[nt][1]);
                    mma16816(cf[mt][nt], ah[mt][0], ah[mt][1], ah[mt][2], ah[mt][3],
                             bl[nt][0], bl[nt][1]);
                    mma16816(cf[mt][nt], al[mt][0], al[mt][1], al[mt][2], al[mt][3],
                             bh[nt][0], bh[nt][1]);
                }
        }
    }
    const int erow = wm * 32 + (lane >> 2);
    const int ecol = wn * 16 + (lane & 3) * 2;
#pragma unroll
    for (int mt = 0; mt < 2; mt++)
#pragma unroll
        for (int nt = 0; nt < 2; nt++) {
            int r = m0 + erow + mt * 16, c = n0 + ecol + nt * 8;
            *(__half2*)&g_ep_h[(size_t)r * AA + c] = __floats2half2_rn(cf[mt][nt][0], cf[mt][nt][1]);
            *(__half2*)&g_ep_h[(size_t)(r + 8) * AA + c] = __floats2half2_rn(cf[mt][nt][2], cf[mt][nt][3]);
        }
}

// ---------------- fused attention (per step) + prev-step fc2 finalize ----------------
__global__ __launch_bounds__(256) void attn_step(const float* __restrict__ v,
                                                 float* __restrict__ attn_out,
                                                 const float* __restrict__ bfc2,
                                                 float* __restrict__ outs, int s) {
    __shared__ float s_dp[256];
    __shared__ float s_v[256];
    __shared__ float s_sc[512];
    __shared__ float s_red[8];
    __shared__ float2 s_cp[2][128];
    const int b = blockIdx.x;
    const int tid = threadIdx.x;
    const int lane = tid & 31, w = tid >> 5;

    if (s > 0 && tid == 0) {
        const float4 p = *(const float4*)&g_fcp4[b * 4];
        float o = (p.x + p.y) + (p.z + p.w) + bfc2[0];
        outs[b * TPRED + (s - 1)] = o;
        g_dec_in[b] = o;
    }

    s_dp[tid] = g_dp[b * 256 + tid];
    s_v[tid] = v[tid];
    __syncthreads();

    float vr[8], dr[8];
#pragma unroll
    for (int i = 0; i < 8; i++) {
        vr[i] = s_v[lane * 8 + i];
        dr[i] = s_dp[lane * 8 + i];
    }

    const __half* ep = g_ep_h + (size_t)b * THIST * AA;
    for (int t = w * 2; t < THIST; t += 16) {
        int4 raw0 = *(const int4*)(ep + (size_t)t * AA + lane * 8);
        int4 raw1 = *(const int4*)(ep + (size_t)(t + 1) * AA + lane * 8);
        const __half2* h0p = (const __half2*)&raw0;
        const __half2* h1p = (const __half2*)&raw1;
        float s0 = 0.f, s1 = 0.f;
#pragma unroll
        for (int q = 0; q < 4; q++) {
            float2 f0 = __half22float2(h0p[q]);
            float2 f1 = __half22float2(h1p[q]);
            s0 = fmaf(vr[2 * q + 0], ftanh_fast(f0.x + dr[2 * q + 0]), s0);
            s0 = fmaf(vr[2 * q + 1], ftanh_fast(f0.y + dr[2 * q + 1]), s0);
            s1 = fmaf(vr[2 * q + 0], ftanh_fast(f1.x + dr[2 * q + 0]), s1);
            s1 = fmaf(vr[2 * q + 1], ftanh_fast(f1.y + dr[2 * q + 1]), s1);
        }
#pragma unroll
        for (int off = 16; off; off >>= 1) {
            s0 += __shfl_xor_sync(0xffffffffu, s0, off);
            s1 += __shfl_xor_sync(0xffffffffu, s1, off);
        }
        if (lane == 0) {
            s_sc[t] = s0;
            s_sc[t + 1] = s1;
        }
    }
    __syncthreads();

    float m = fmaxf(s_sc[tid], s_sc[tid + 256]);
#pragma unroll
    for (int off = 16; off; off >>= 1) m = fmaxf(m, __shfl_xor_sync(0xffffffffu, m, off));
    if (lane == 0) s_red[w] = m;
    __syncthreads();
    float mm = s_red[0];
#pragma unroll
    for (int i = 1; i < 8; i++) mm = fmaxf(mm, s_red[i]);
    float e0 = __expf(s_sc[tid] - mm);
    float e1 = __expf(s_sc[tid + 256] - mm);
    float sm = e0 + e1;
#pragma unroll
    for (int off = 16; off; off >>= 1) sm += __shfl_xor_sync(0xffffffffu, sm, off);
    __syncthreads();
    if (lane == 0) s_red[w] = sm;
    __syncthreads();
    float tot = s_red[0];
#pragma unroll
    for (int i = 1; i < 8; i++) tot += s_red[i];
    float inv = 1.f / tot;
    float p0 = e0 * inv, p1 = e1 * inv;
    s_sc[tid] = p0;
    s_sc[tid + 256] = p1;
    attn_out[(size_t)b * THIST + tid] = p0;
    attn_out[(size_t)b * THIST + tid + 256] = p1;
    __syncthreads();

    const int e2 = tid & 127;
    const int tpar = tid >> 7;
    const __half2* eoh2 = (const __half2*)(g_eo_h + (size_t)b * THIST * HENC);
    float cx = 0.f, cy = 0.f;
#pragma unroll 4
    for (int t = tpar; t < THIST; t += 2) {
        float2 f = __half22float2(eoh2[(size_t)t * 128 + e2]);
        float p = s_sc[t];
        cx = fmaf(p, f.x, cx);
        cy = fmaf(p, f.y, cy);
    }
    s_cp[tpar][e2] = make_float2(cx, cy);
    __syncthreads();

    const int e = tid;
    const int ee2 = e >> 1;
    float cacc = (e & 1) ? (s_cp[0][ee2].y + s_cp[1][ee2].y)
                         : (s_cp[0][ee2].x + s_cp[1][ee2].x);
    g_xcat0h[b * 512 + e] = __float2half(cacc);
    g_xcat0h[b * 512 + 256 + e] = __float2half(g_h0[b * 256 + e]);
    g_xcatfch[b * 512 + 256 + e] = __float2half(cacc);
}

// ---------------- fp16 MMA 64x64 tile GEMM core ----------------
__device__ void gemm_mma_64x64(const __half* __restrict__ A, int lda,
                               const __half* __restrict__ B, int ldb,
                               int m0, int n0, int ktot, float cf[2][2][4]) {
    static __shared__ __half sA[64 * 40];
    static __shared__ __half sB[64 * 40];
    const int tid = threadIdx.x, lane = tid & 31, wid = tid >> 5;
    const int wm = wid & 1, wn = wid >> 1;
#pragma unroll
    for (int mt = 0; mt < 2; mt++)
#pragma unroll
        for (int nt = 0; nt < 2; nt++)
#pragma unroll
            for (int q = 0; q < 4; q++) cf[mt][nt][q] = 0.f;
    const int lrow = tid >> 2, lcol = (tid & 3) * 8;
    const uint32_t aBase = smem_u32(sA), bBase = smem_u32(sB);
    const int arow = wm * 32 + (lane & 15);
    const int acol8 = 8 * (lane >> 4);
    const int brow = wn * 16 + (lane & 7);
    const int bcol8 = 8 * ((lane >> 3) & 1);

    for (int kc = 0; kc < ktot; kc += 32) {
        __syncthreads();
        *(uint4*)&sA[lrow * 40 + lcol] = *(const uint4*)&A[(size_t)(m0 + lrow) * lda + kc + lcol];
        *(uint4*)&sB[lrow * 40 + lcol] = *(const uint4*)&B[(size_t)(n0 + lrow) * ldb + kc + lcol];
        __syncthreads();
#pragma unroll
        for (int ks = 0; ks < 32; ks += 16) {
            uint32_t a[2][4], bfrag[2][2];
#pragma unroll
            for (int mt = 0; mt < 2; mt++) {
                ldsm_x4(aBase + ((arow + mt * 16) * 40 + ks + acol8) * 2,
                        a[mt][0], a[mt][1], a[mt][2], a[mt][3]);
            }
#pragma unroll
            for (int nt = 0; nt < 2; nt++) {
                ldsm_x2(bBase + ((brow + nt * 8) * 40 + ks + bcol8) * 2,
                        bfrag[nt][0], bfrag[nt][1]);
            }
#pragma unroll
            for (int mt = 0; mt < 2; mt++)
#pragma unroll
                for (int nt = 0; nt < 2; nt++)
                    mma16816(cf[mt][nt], a[mt][0], a[mt][1], a[mt][2], a[mt][3],
                             bfrag[nt][0], bfrag[nt][1]);
        }
    }
}

// ---------------- fused recurrent step: 3 phases, 2 barriers ----------------
__global__ __launch_bounds__(256) void recurrent_step(const float* __restrict__ bfc1,
                                                      const float* __restrict__ Wfc2) {
    unsigned eps = 0;
    if (threadIdx.x == 0) eps = atomicAdd(&g_sense, 0);
    const int cta = blockIdx.x;
    const int tid = threadIdx.x;
    const int lane = tid & 31, wid = tid >> 5;
    const int wm = wid & 1, wn = wid >> 1;
    const int parity = lane & 1;
    float cf[2][2][4];

    // ===== P0: lstm0 gates GEMM + cell0 epilogue (gate-interleaved) =====
    {
        const int m0 = (cta & 7) * 64, n0 = (cta >> 3) * 64;
        gemm_mma_64x64(g_xcat0h, 512, g_Wcat0rh, 512, m0, n0, 512, cf);
#pragma unroll
        for (int mt = 0; mt < 2; mt++)
#pragma unroll
            for (int nt = 0; nt < 2; nt++) {
                float t0 = __shfl_xor_sync(0xffffffffu, cf[mt][nt][0], 1);
                float t1 = __shfl_xor_sync(0xffffffffu, cf[mt][nt][1], 1);
                float t2 = __shfl_xor_sync(0xffffffffu, cf[mt][nt][2], 1);
                float t3 = __shfl_xor_sync(0xffffffffu, cf[mt][nt][3], 1);
                const int c = n0 + wn * 16 + (lane & 3) * 2 + nt * 8;
                const int j = c >> 2;
                const int r = m0 + wm * 32 + (lane >> 2) + mt * 16;
                int b;
                float gi, gf, gg, go;
                if (!parity) { b = r;     gi = cf[mt][nt][0]; gf = cf[mt][nt][1]; gg = t0; go = t1; }
                else         { b = r + 8; gi = t2;            gf = t3;            gg = cf[mt][nt][2]; go = cf[mt][nt][3]; }
                const float din = g_dec_in[b];
                const float4 wc = *(const float4*)&g_wcol0r[4 * j];
                const float4 bs = *(const float4*)&g_bias0r[4 * j];
                gi += din * wc.x + bs.x;
                gf += din * wc.y + bs.y;
                gg += din * wc.z + bs.z;
                go += din * wc.w + bs.w;
                const int idx = b * 256 + j;
                float cc = sig_precise(gf) * g_c0[idx] + sig_precise(gi) * tanhf(gg);
                float hh = sig_precise(go) * tanhf(cc);
                g_c0[idx] = cc;
                g_h0[idx] = hh;
                g_xcat1h[b * 512 + j] = __float2half(hh);
                g_xcat1h[b * 512 + 256 + j] = __float2half(g_h1[idx]);
            }
    }
    grid_barrier(&eps);

    // ===== P1: lstm1 gates GEMM + cell1 epilogue =====
    {
        const int m0 = (cta & 7) * 64, n0 = (cta >> 3) * 64;
        gemm_mma_64x64(g_xcat1h, 512, g_Wcat1rh, 512, m0, n0, 512, cf);
#pragma unroll
        for (int mt = 0; mt < 2; mt++)
#pragma unroll
            for (int nt = 0; nt < 2; nt++) {
                float t0 = __shfl_xor_sync(0xffffffffu, cf[mt][nt][0], 1);
                float t1 = __shfl_xor_sync(0xffffffffu, cf[mt][nt][1], 1);
                float t2 = __shfl_xor_sync(0xffffffffu, cf[mt][nt][2], 1);
                float t3 = __shfl_xor_sync(0xffffffffu, cf[mt][nt][3], 1);
                const int c = n0 + wn * 16 + (lane & 3) * 2 + nt * 8;
                const int j = c >> 2;
                const int r = m0 + wm * 32 + (lane >> 2) + mt * 16;
                int b;
                float gi, gf, gg, go;
                if (!parity) { b = r;     gi = cf[mt][nt][0]; gf = cf[mt][nt][1]; gg = t0; go = t1; }
                else         { b = r + 8; gi = t2;            gf = t3;            gg = cf[mt][nt][2]; go = cf[mt][nt][3]; }
                const float4 bs = *(const float4*)&g_bias1r[4 * j];
                gi += bs.x;
                gf += bs.y;
                gg += bs.z;
                go += bs.w;
                const int idx = b * 256 + j;
                float cc = sig_precise(gf) * g_c1[idx] + sig_precise(gi) * tanhf(gg);
                float hh = sig_precise(go) * tanhf(cc);
                g_c1[idx] = cc;
                g_h1[idx] = hh;
                g_xcatfch[b * 512 + j] = __float2half(hh);
            }
    }
    grid_barrier(&eps);

    // ===== P2: fc1+relu+Wfc2 partial (ctas 0-31) | dec_proj (ctas 32-63) =====
    if (cta < 32) {
        __shared__ float sfc[64][4];
        const int m0 = (cta & 7) * 64, n0 = (cta >> 3) * 64;
        gemm_mma_64x64(g_xcatfch, 512, g_Wfc1h, 512, m0, n0, 512, cf);
        float s0[2] = {0.f, 0.f}, s1[2] = {0.f, 0.f};  // [mt] for rows r, r+8
#pragma unroll
        for (int mt = 0; mt < 2; mt++)
#pragma unroll
            for (int nt = 0; nt < 2; nt++) {
                const int c = n0 + wn * 16 + (lane & 3) * 2 + nt * 8;
                const float b0 = bfc1[c], b1 = bfc1[c + 1];
                const float w0 = Wfc2[c], w1 = Wfc2[c + 1];
                s0[mt] += fmaxf(cf[mt][nt][0] + b0, 0.f) * w0 + fmaxf(cf[mt][nt][1] + b1, 0.f) * w1;
                s1[mt] += fmaxf(cf[mt][nt][2] + b0, 0.f) * w0 + fmaxf(cf[mt][nt][3] + b1, 0.f) * w1;
            }
        // reduce over lane&3 (the 4 column sub-lanes)
#pragma unroll
        for (int off = 1; off < 4; off <<= 1) {
#pragma unroll
            for (int mt = 0; mt < 2; mt++) {
                s0[mt] += __shfl_xor_sync(0xffffffffu, s0[mt], off);
                s1[mt] += __shfl_xor_sync(0xffffffffu, s1[mt], off);
            }
        }
        if ((lane & 3) == 0) {
#pragma unroll
            for (int mt = 0; mt < 2; mt++) {
                int rl = wm * 32 + (lane >> 2) + mt * 16;
                // accumulate 4 wn-warps into smem via separate slots
                sfc[rl][wn] = s0[mt];
                sfc[rl + 8][wn] = s1[mt];
            }
        }
        __syncthreads();
        if (tid < 64) {
            float p = sfc[tid][0] + sfc[tid][1] + sfc[tid][2] + sfc[tid][3];
            g_fcp4[(m0 + tid) * 4 + (cta >> 3)] = p;
        }
    } else if (cta < 64) {
        const int c2 = cta - 32;
        const int m0 = (c2 & 7) * 64, n0 = (c2 >> 3) * 64;
        gemm_mma_64x64(g_xcatfch, 512, g_Wt_dech, 256, m0, n0, 256, cf);
        const int erow = wm * 32 + (lane >> 2);
        const int ecol = wn * 16 + (lane & 3) * 2;
#pragma unroll
        for (int mt = 0; mt < 2; mt++)
#pragma unroll
            for (int nt = 0; nt < 2; nt++) {
                int r = m0 + erow + mt * 16, c = n0 + ecol + nt * 8;
                *(float2*)&g_dp[(size_t)r * AA + c] = make_float2(cf[mt][nt][0], cf[mt][nt][1]);
                *(float2*)&g_dp[(size_t)(r + 8) * AA + c] = make_float2(cf[mt][nt][2], cf[mt][nt][3]);
            }
    }
}

// ---------------- finalize last step's fc output ----------------
__global__ void finalize(const float* __restrict__ bfc2, float* __restrict__ outs) {
    int b = blockIdx.x * 256 + threadIdx.x;
    const float4 p = *(const float4*)&g_fcp4[b * 4];
    outs[b * TPRED + (TPRED - 1)] = (p.x + p.y) + (p.z + p.w) + bfc2[0];
}

// ---------------- initial dec_proj from encoder_hidden[1] ----------------
__global__ __launch_bounds__(256) void dp_init(const float* __restrict__ Wad) {
    __shared__ float sA[8][256];
    const int b0 = blockIdx.x * 8;
    const int tid = threadIdx.x;
#pragma unroll
    for (int q = 0; q < 2; q++) {
        int f4 = q * 256 + tid;
        int r = f4 >> 6, c = (f4 & 63) * 4;
        *(float4*)&sA[r][c] = *(const float4*)&g_h1[(size_t)(b0 + r) * 256 + c];
    }
    __syncthreads();
    float dpa[8];
#pragma unroll
    for (int r = 0; r < 8; r++) dpa[r] = 0.f;
#pragma unroll 4
    for (int h = 0; h < 256; h++) {
        const float wv = Wad[(size_t)h * AA + tid];
#pragma unroll
        for (int r = 0; r < 8; r++) dpa[r] = fmaf(sA[r][h], wv, dpa[r]);
    }
#pragma unroll
    for (int r = 0; r < 8; r++) g_dp[(b0 + r) * 256 + tid] = dpa[r];
}

// ---------------- host launcher ----------------
extern "C" void kernel_launch(void* const* d_in, const int* in_sizes, int n_in,
                              void* d_out, int out_size) {
    int off = (in_sizes[0] == 1) ? 1 : 0;
    const float* enc_out = (const float*)d_in[off + 0];
    const float* enc_h = (const float*)d_in[off + 1];
    const float* enc_c = (const float*)d_in[off + 2];
    const float* Wae = (const float*)d_in[off + 3];
    const float* Wad = (const float*)d_in[off + 4];
    const float* v = (const float*)d_in[off + 5];
    const float* Wih0 = (const float*)d_in[off + 6];
    const float* Whh0 = (const float*)d_in[off + 7];
    const float* bih0 = (const float*)d_in[off + 8];
    const float* bhh0 = (const float*)d_in[off + 9];
    const float* Wih1 = (const float*)d_in[off + 10];
    const float* Whh1 = (const float*)d_in[off + 11];
    const float* bih1 = (const float*)d_in[off + 12];
    const float* bhh1 = (const float*)d_in[off + 13];
    const float* Wfc1 = (const float*)d_in[off + 14];
    const float* bfc1 = (const float*)d_in[off + 15];
    const float* Wfc2 = (const float*)d_in[off + 16];
    const float* bfc2 = (const float*)d_in[off + 17];

    float* out = (float*)d_out;
    float* attn_base = out + (size_t)BB * TPRED;

    init_state<<<(BB * HH + 255) / 256, 256>>>(enc_h, enc_c);
    prep<<<2048, 256>>>(Wae, Wad, Wih0, Whh0, bih0, bhh0, Wih1, Whh1, bih1, bhh1, Wfc1);
    prep_eo<<<(BB * THIST * HENC / 4) / 256, 256>>>(enc_out);
    encproj_mma<<<dim3(4, 4096), 256>>>();
    dp_init<<<BB / 8, 256>>>(Wad);

    for (int s = 0; s < TPRED; s++) {
        attn_step<<<BB, 256>>>(v, attn_base + (size_t)s * BB * THIST, bfc2, out, s);
        recurrent_step<<<NCTAS, 256>>>(bfc1, Wfc2);
    }
    finalize<<<2, 256>>>(bfc2, out);
    (void)n_in;
    (void)out_size;
}

// round 6
// speedup vs baseline: 2.2748x; 1.4027x over previous
#include <cuda_runtime.h>
#include <cuda_fp16.h>
#include <cstdint>

#define BB 512
#define THIST 512
#define HENC 256
#define HH 256
#define AA 256
#define TPRED 32
#define NG 1024
#define NCTAS 128

// ---------------- device scratch (static only) ----------------
__device__ __half g_ep_h[(size_t)BB * THIST * AA];    // enc_proj fp16
__device__ __half g_eo_h[(size_t)BB * THIST * HENC];  // encoder_outputs fp16 hi
__device__ __half g_eo_l[(size_t)BB * THIST * HENC];  // fp16 lo residual
__device__ __half g_Wt_ench[HENC * AA];               // [a][e] fp16
__device__ __half g_Wcat0rh[NG * 512];                // gate-interleaved n'=4j+g
__device__ __half g_Wcat1rh[NG * 512];
__device__ __half g_Wfc1h[HH * 512];
__device__ __half g_Wt_dech[AA * HH];                 // [a][h]
__device__ float g_wcol0r[NG];
__device__ float g_bias0r[NG];
__device__ float g_bias1r[NG];
__device__ float g_h0[BB * HH], g_h1[BB * HH];
__device__ float g_c0[BB * HH], g_c1[BB * HH];
__device__ float g_dec_in[BB];
__device__ float g_dp[BB * AA];
__device__ float g_fcp4[BB * 4];
__device__ __half g_xcat0h[BB * 512];                 // [ctx | h0_old]
__device__ __half g_xcat1h[BB * 512];                 // [h0_new | h1_old]
__device__ __half g_xcatfch[BB * 512];                // [h1_new | ctx]

__device__ unsigned g_count = 0;
__device__ unsigned g_sense = 0;

// ---------------- helpers ----------------
__device__ __forceinline__ float ftanh_fast(float x) {
    float y;
    asm("tanh.approx.f32 %0, %1;" : "=f"(y) : "f"(x));
    return y;
}
__device__ __forceinline__ float sig_precise(float x) { return 1.f / (1.f + expf(-x)); }

__device__ __forceinline__ uint32_t smem_u32(const void* p) {
    uint32_t a;
    asm("{.reg .u64 t; cvta.to.shared.u64 t, %1; cvt.u32.u64 %0, t;}" : "=r"(a) : "l"(p));
    return a;
}
__device__ __forceinline__ void ldsm_x4(uint32_t addr, uint32_t& r0, uint32_t& r1,
                                        uint32_t& r2, uint32_t& r3) {
    asm volatile("ldmatrix.sync.aligned.m8n8.x4.shared.b16 {%0,%1,%2,%3}, [%4];"
                 : "=r"(r0), "=r"(r1), "=r"(r2), "=r"(r3) : "r"(addr));
}
__device__ __forceinline__ void ldsm_x2(uint32_t addr, uint32_t& r0, uint32_t& r1) {
    asm volatile("ldmatrix.sync.aligned.m8n8.x2.shared.b16 {%0,%1}, [%2];"
                 : "=r"(r0), "=r"(r1) : "r"(addr));
}
__device__ __forceinline__ void mma16816(float* d, uint32_t a0, uint32_t a1, uint32_t a2,
                                         uint32_t a3, uint32_t b0, uint32_t b1) {
    asm volatile(
        "mma.sync.aligned.m16n8k16.row.col.f32.f16.f16.f32 "
        "{%0,%1,%2,%3},{%4,%5,%6,%7},{%8,%9},{%0,%1,%2,%3};"
        : "+f"(d[0]), "+f"(d[1]), "+f"(d[2]), "+f"(d[3])
        : "r"(a0), "r"(a1), "r"(a2), "r"(a3), "r"(b0), "r"(b1));
}

__device__ __forceinline__ void grid_barrier(unsigned* eps) {
    __syncthreads();
    if (threadIdx.x == 0) {
        unsigned target = ++(*eps);
        __threadfence();
        unsigned old = atomicAdd(&g_count, 1);
        if (old == NCTAS - 1) {
            g_count = 0;
            __threadfence();
            atomicExch(&g_sense, target);
        } else {
            while (atomicAdd(&g_sense, 0) != target) __nanosleep(64);
        }
    }
    __syncthreads();
}

// ---------------- init + prep ----------------
__global__ void init_state(const float* __restrict__ eh, const float* __restrict__ ec) {
    int i = blockIdx.x * blockDim.x + threadIdx.x;
    if (i < BB * HH) {
        g_h0[i] = eh[i];
        g_h1[i] = eh[BB * HH + i];
        g_c0[i] = ec[i];
        g_c1[i] = ec[BB * HH + i];
    }
    if (i < BB) g_dec_in[i] = 0.f;
}

__global__ void prep(const float* __restrict__ Wae, const float* __restrict__ Wad,
                     const float* __restrict__ Wih0, const float* __restrict__ Whh0,
                     const float* __restrict__ bih0, const float* __restrict__ bhh0,
                     const float* __restrict__ Wih1, const float* __restrict__ Whh1,
                     const float* __restrict__ bih1, const float* __restrict__ bhh1,
                     const float* __restrict__ Wfc1) {
    int i = blockIdx.x * blockDim.x + threadIdx.x;
    if (i < HENC * AA) {
        int a = i / HENC, e = i % HENC;
        g_Wt_ench[i] = __float2half(Wae[e * AA + a]);
    }
    if (i < NG * 512) {
        int n4 = i >> 9, c = i & 511;
        int j = n4 >> 2, g = n4 & 3;
        int n = g * 256 + j;
        g_Wcat0rh[i] = __float2half((c < 256) ? Wih0[n * 257 + 1 + c] : Whh0[n * 256 + (c - 256)]);
        g_Wcat1rh[i] = __float2half((c < 256) ? Wih1[n * 256 + c] : Whh1[n * 256 + (c - 256)]);
    }
    if (i < HH * 512) g_Wfc1h[i] = __float2half(Wfc1[i]);
    if (i < AA * HH) {
        int a = i >> 8, h = i & 255;
        g_Wt_dech[i] = __float2half(Wad[h * AA + a]);
    }
    if (i < NG) {
        int j = i >> 2, g = i & 3;
        int n = g * 256 + j;
        g_wcol0r[i] = Wih0[n * 257];
        g_bias0r[i] = bih0[n] + bhh0[n];
        g_bias1r[i] = bih1[n] + bhh1[n];
    }
}

__global__ void prep_eo(const float* __restrict__ eo) {
    int i = blockIdx.x * blockDim.x + threadIdx.x;
    const float4 v = ((const float4*)eo)[i];
    __half h0 = __float2half(v.x), h1 = __float2half(v.y);
    __half h2 = __float2half(v.z), h3 = __float2half(v.w);
    __half2 hhi[2] = {__halves2half2(h0, h1), __halves2half2(h2, h3)};
    __half2 hlo[2] = {
        __floats2half2_rn(v.x - __half2float(h0), v.y - __half2float(h1)),
        __floats2half2_rn(v.z - __half2float(h2), v.w - __half2float(h3))};
    ((uint2*)g_eo_h)[i] = *(uint2*)hhi;
    ((uint2*)g_eo_l)[i] = *(uint2*)hlo;
}

// ---------------- enc_proj: TC, A hi/lo x B hi (2 MMA), double-buffered ----------------
__global__ __launch_bounds__(256) void encproj_mma() {
    __shared__ __half sAh[2][64 * 40], sAl[2][64 * 40], sBh[2][64 * 40];
    const int m0 = blockIdx.y * 64;
    const int n0 = blockIdx.x * 64;
    const int tid = threadIdx.x, lane = tid & 31, wid = tid >> 5;
    const int wm = wid & 1, wn = wid >> 1;
    float cf[2][2][4];
#pragma unroll
    for (int mt = 0; mt < 2; mt++)
#pragma unroll
        for (int nt = 0; nt < 2; nt++)
#pragma unroll
            for (int q = 0; q < 4; q++) cf[mt][nt][q] = 0.f;
    const int lrow = tid >> 2, lcol = (tid & 3) * 8;
    const uint32_t ahB = smem_u32(sAh), alB = smem_u32(sAl), bhB = smem_u32(sBh);
    const int arow = wm * 32 + (lane & 15);
    const int acol8 = 8 * (lane >> 4);
    const int brow = wn * 16 + (lane & 7);
    const int bcol8 = 8 * ((lane >> 3) & 1);

    uint4 rah = *(const uint4*)&g_eo_h[(size_t)(m0 + lrow) * 256 + lcol];
    uint4 ral = *(const uint4*)&g_eo_l[(size_t)(m0 + lrow) * 256 + lcol];
    uint4 rbh = *(const uint4*)&g_Wt_ench[(size_t)(n0 + lrow) * 256 + lcol];
#pragma unroll
    for (int it = 0; it < 8; it++) {
        const int buf = it & 1;
        *(uint4*)&sAh[buf][lrow * 40 + lcol] = rah;
        *(uint4*)&sAl[buf][lrow * 40 + lcol] = ral;
        *(uint4*)&sBh[buf][lrow * 40 + lcol] = rbh;
        __syncthreads();
        if (it < 7) {
            const int kc = (it + 1) * 32;
            rah = *(const uint4*)&g_eo_h[(size_t)(m0 + lrow) * 256 + kc + lcol];
            ral = *(const uint4*)&g_eo_l[(size_t)(m0 + lrow) * 256 + kc + lcol];
            rbh = *(const uint4*)&g_Wt_ench[(size_t)(n0 + lrow) * 256 + kc + lcol];
        }
        const uint32_t off = buf * (64 * 40) * 2;
#pragma unroll
        for (int ks = 0; ks < 32; ks += 16) {
            uint32_t ah[2][4], al[2][4], bh[2][2];
#pragma unroll
            for (int mt = 0; mt < 2; mt++) {
                ldsm_x4(ahB + off + ((arow + mt * 16) * 40 + ks + acol8) * 2,
                        ah[mt][0], ah[mt][1], ah[mt][2], ah[mt][3]);
                ldsm_x4(alB + off + ((arow + mt * 16) * 40 + ks + acol8) * 2,
                        al[mt][0], al[mt][1], al[mt][2], al[mt][3]);
            }
#pragma unroll
            for (int nt = 0; nt < 2; nt++)
                ldsm_x2(bhB + off + ((brow + nt * 8) * 40 + ks + bcol8) * 2, bh[nt][0], bh[nt][1]);
#pragma unroll
            for (int mt = 0; mt < 2; mt++)
#pragma unroll
                for (int nt = 0; nt < 2; nt++) {
                    mma16816(cf[mt][nt], ah[mt][0], ah[mt][1], ah[mt][2], ah[mt][3],
                             bh[nt][0], bh[nt][1]);
                    mma16816(cf[mt][nt], al[mt][0], al[mt][1], al[mt][2], al[mt][3],
                             bh[nt][0], bh[nt][1]);
                }
        }
    }
    const int erow = wm * 32 + (lane >> 2);
    const int ecol = wn * 16 + (lane & 3) * 2;
#pragma unroll
    for (int mt = 0; mt < 2; mt++)
#pragma unroll
        for (int nt = 0; nt < 2; nt++) {
            int r = m0 + erow + mt * 16, c = n0 + ecol + nt * 8;
            *(__half2*)&g_ep_h[(size_t)r * AA + c] = __floats2half2_rn(cf[mt][nt][0], cf[mt][nt][1]);
            *(__half2*)&g_ep_h[(size_t)(r + 8) * AA + c] = __floats2half2_rn(cf[mt][nt][2], cf[mt][nt][3]);
        }
}

// ---------------- fused attention (per step) + prev-step fc2 finalize ----------------
__global__ __launch_bounds__(256) void attn_step(const float* __restrict__ v,
                                                 float* __restrict__ attn_out,
                                                 const float* __restrict__ bfc2,
                                                 float* __restrict__ outs, int s) {
    __shared__ float s_dp[256];
    __shared__ float s_v[256];
    __shared__ float s_sc[512];
    __shared__ float s_red[8];
    __shared__ float s_ctx[8][256];
    const int b = blockIdx.x;
    const int tid = threadIdx.x;
    const int lane = tid & 31, w = tid >> 5;

    if (s > 0 && tid == 0) {
        const float4 p = *(const float4*)&g_fcp4[b * 4];
        float o = (p.x + p.y) + (p.z + p.w) + bfc2[0];
        outs[b * TPRED + (s - 1)] = o;
        g_dec_in[b] = o;
    }

    s_dp[tid] = g_dp[b * 256 + tid];
    s_v[tid] = v[tid];
    __syncthreads();

    float vr[8], dr[8];
#pragma unroll
    for (int i = 0; i < 8; i++) {
        vr[i] = s_v[lane * 8 + i];
        dr[i] = s_dp[lane * 8 + i];
    }

    // ---- scores: 4 rows per warp-iter (4 LDG.128 in flight per lane) ----
    const __half* ep = g_ep_h + (size_t)b * THIST * AA;
    for (int t0 = w * 4; t0 < THIST; t0 += 32) {
        int4 raw[4];
#pragma unroll
        for (int u = 0; u < 4; u++)
            raw[u] = *(const int4*)(ep + (size_t)(t0 + u) * AA + lane * 8);
        float ss[4];
#pragma unroll
        for (int u = 0; u < 4; u++) {
            const __half2* hp = (const __half2*)&raw[u];
            float acc = 0.f;
#pragma unroll
            for (int q = 0; q < 4; q++) {
                float2 f = __half22float2(hp[q]);
                acc = fmaf(vr[2 * q + 0], ftanh_fast(f.x + dr[2 * q + 0]), acc);
                acc = fmaf(vr[2 * q + 1], ftanh_fast(f.y + dr[2 * q + 1]), acc);
            }
            ss[u] = acc;
        }
#pragma unroll
        for (int off = 16; off; off >>= 1)
#pragma unroll
            for (int u = 0; u < 4; u++) ss[u] += __shfl_xor_sync(0xffffffffu, ss[u], off);
        if (lane == 0) {
            s_sc[t0 + 0] = ss[0];
            s_sc[t0 + 1] = ss[1];
            s_sc[t0 + 2] = ss[2];
            s_sc[t0 + 3] = ss[3];
        }
    }
    __syncthreads();

    // ---- softmax over 512 ----
    float m = fmaxf(s_sc[tid], s_sc[tid + 256]);
#pragma unroll
    for (int off = 16; off; off >>= 1) m = fmaxf(m, __shfl_xor_sync(0xffffffffu, m, off));
    if (lane == 0) s_red[w] = m;
    __syncthreads();
    float mm = s_red[0];
#pragma unroll
    for (int i = 1; i < 8; i++) mm = fmaxf(mm, s_red[i]);
    float e0 = __expf(s_sc[tid] - mm);
    float e1 = __expf(s_sc[tid + 256] - mm);
    float sm = e0 + e1;
#pragma unroll
    for (int off = 16; off; off >>= 1) sm += __shfl_xor_sync(0xffffffffu, sm, off);
    __syncthreads();
    if (lane == 0) s_red[w] = sm;
    __syncthreads();
    float tot = s_red[0];
#pragma unroll
    for (int i = 1; i < 8; i++) tot += s_red[i];
    float inv = 1.f / tot;
    float p0 = e0 * inv, p1 = e1 * inv;
    s_sc[tid] = p0;
    s_sc[tid + 256] = p1;
    attn_out[(size_t)b * THIST + tid] = p0;
    attn_out[(size_t)b * THIST + tid + 256] = p1;
    __syncthreads();

    // ---- ctx: lane covers 8 e's (int4/row), 8 independent rows in flight ----
    const __half* eob = g_eo_h + (size_t)b * THIST * HENC;
    float cacc[8];
#pragma unroll
    for (int q = 0; q < 8; q++) cacc[q] = 0.f;
    for (int i0 = 0; i0 < 64; i0 += 8) {
        int4 r[8];
        float p[8];
#pragma unroll
        for (int u = 0; u < 8; u++) {
            int t = w + (i0 + u) * 8;
            r[u] = *(const int4*)(eob + (size_t)t * HENC + lane * 8);
            p[u] = s_sc[t];
        }
#pragma unroll
        for (int u = 0; u < 8; u++) {
            const __half2* hp = (const __half2*)&r[u];
#pragma unroll
            for (int q = 0; q < 4; q++) {
                float2 f = __half22float2(hp[q]);
                cacc[2 * q + 0] = fmaf(p[u], f.x, cacc[2 * q + 0]);
                cacc[2 * q + 1] = fmaf(p[u], f.y, cacc[2 * q + 1]);
            }
        }
    }
#pragma unroll
    for (int q = 0; q < 8; q++) s_ctx[w][lane * 8 + q] = cacc[q];
    __syncthreads();

    const int e = tid;
    float csum = 0.f;
#pragma unroll
    for (int q = 0; q < 8; q++) csum += s_ctx[q][e];
    g_xcat0h[b * 512 + e] = __float2half(csum);
    g_xcat0h[b * 512 + 256 + e] = __float2half(g_h0[b * 256 + e]);
    g_xcatfch[b * 512 + 256 + e] = __float2half(csum);
}

// ---------------- double-buffered fp16 MMA 64x64 tile GEMM core ----------------
__device__ void gemm_mma_db(const __half* __restrict__ A, int lda,
                            const __half* __restrict__ B, int ldb,
                            int m0, int n0, int ktot, float cf[2][2][4]) {
    static __shared__ __half sA[2][64 * 40];
    static __shared__ __half sB[2][64 * 40];
    const int tid = threadIdx.x, lane = tid & 31, wid = tid >> 5;
    const int wm = wid & 1, wn = wid >> 1;
#pragma unroll
    for (int mt = 0; mt < 2; mt++)
#pragma unroll
        for (int nt = 0; nt < 2; nt++)
#pragma unroll
            for (int q = 0; q < 4; q++) cf[mt][nt][q] = 0.f;
    const int lrow = tid >> 2, lcol = (tid & 3) * 8;
    const uint32_t aBase = smem_u32(sA), bBase = smem_u32(sB);
    const int arow = wm * 32 + (lane & 15);
    const int acol8 = 8 * (lane >> 4);
    const int brow = wn * 16 + (lane & 7);
    const int bcol8 = 8 * ((lane >> 3) & 1);
    const int niter = ktot / 32;

    uint4 ra = *(const uint4*)&A[(size_t)(m0 + lrow) * lda + lcol];
    uint4 rb = *(const uint4*)&B[(size_t)(n0 + lrow) * ldb + lcol];
    for (int it = 0; it < niter; it++) {
        const int buf = it & 1;
        *(uint4*)&sA[buf][lrow * 40 + lcol] = ra;
        *(uint4*)&sB[buf][lrow * 40 + lcol] = rb;
        __syncthreads();
        if (it + 1 < niter) {
            const int kc = (it + 1) * 32;
            ra = *(const uint4*)&A[(size_t)(m0 + lrow) * lda + kc + lcol];
            rb = *(const uint4*)&B[(size_t)(n0 + lrow) * ldb + kc + lcol];
        }
        const uint32_t off = buf * (64 * 40) * 2;
#pragma unroll
        for (int ks = 0; ks < 32; ks += 16) {
            uint32_t a[2][4], bfrag[2][2];
#pragma unroll
            for (int mt = 0; mt < 2; mt++)
                ldsm_x4(aBase + off + ((arow + mt * 16) * 40 + ks + acol8) * 2,
                        a[mt][0], a[mt][1], a[mt][2], a[mt][3]);
#pragma unroll
            for (int nt = 0; nt < 2; nt++)
                ldsm_x2(bBase + off + ((brow + nt * 8) * 40 + ks + bcol8) * 2,
                        bfrag[nt][0], bfrag[nt][1]);
#pragma unroll
            for (int mt = 0; mt < 2; mt++)
#pragma unroll
                for (int nt = 0; nt < 2; nt++)
                    mma16816(cf[mt][nt], a[mt][0], a[mt][1], a[mt][2], a[mt][3],
                             bfrag[nt][0], bfrag[nt][1]);
        }
    }
}

// ---------------- fused recurrent step: 3 phases, 2 barriers ----------------
__global__ __launch_bounds__(256) void recurrent_step(const float* __restrict__ bfc1,
                                                      const float* __restrict__ Wfc2) {
    unsigned eps = 0;
    if (threadIdx.x == 0) eps = atomicAdd(&g_sense, 0);
    const int cta = blockIdx.x;
    const int tid = threadIdx.x;
    const int lane = tid & 31, wid = tid >> 5;
    const int wm = wid & 1, wn = wid >> 1;
    const int parity = lane & 1;
    float cf[2][2][4];

    // ===== P0: lstm0 gates GEMM + cell0 epilogue =====
    {
        const int m0 = (cta & 7) * 64, n0 = (cta >> 3) * 64;
        gemm_mma_db(g_xcat0h, 512, g_Wcat0rh, 512, m0, n0, 512, cf);
#pragma unroll
        for (int mt = 0; mt < 2; mt++)
#pragma unroll
            for (int nt = 0; nt < 2; nt++) {
                float t0 = __shfl_xor_sync(0xffffffffu, cf[mt][nt][0], 1);
                float t1 = __shfl_xor_sync(0xffffffffu, cf[mt][nt][1], 1);
                float t2 = __shfl_xor_sync(0xffffffffu, cf[mt][nt][2], 1);
                float t3 = __shfl_xor_sync(0xffffffffu, cf[mt][nt][3], 1);
                const int c = n0 + wn * 16 + (lane & 3) * 2 + nt * 8;
                const int j = c >> 2;
                const int r = m0 + wm * 32 + (lane >> 2) + mt * 16;
                int b;
                float gi, gf, gg, go;
                if (!parity) { b = r;     gi = cf[mt][nt][0]; gf = cf[mt][nt][1]; gg = t0; go = t1; }
                else         { b = r + 8; gi = t2;            gf = t3;            gg = cf[mt][nt][2]; go = cf[mt][nt][3]; }
                const float din = g_dec_in[b];
                const float4 wc = *(const float4*)&g_wcol0r[4 * j];
                const float4 bs = *(const float4*)&g_bias0r[4 * j];
                gi += din * wc.x + bs.x;
                gf += din * wc.y + bs.y;
                gg += din * wc.z + bs.z;
                go += din * wc.w + bs.w;
                const int idx = b * 256 + j;
                float cc = sig_precise(gf) * g_c0[idx] + sig_precise(gi) * tanhf(gg);
                float hh = sig_precise(go) * tanhf(cc);
                g_c0[idx] = cc;
                g_h0[idx] = hh;
                g_xcat1h[b * 512 + j] = __float2half(hh);
                g_xcat1h[b * 512 + 256 + j] = __float2half(g_h1[idx]);
            }
    }
    grid_barrier(&eps);

    // ===== P1: lstm1 gates GEMM + cell1 epilogue =====
    {
        const int m0 = (cta & 7) * 64, n0 = (cta >> 3) * 64;
        gemm_mma_db(g_xcat1h, 512, g_Wcat1rh, 512, m0, n0, 512, cf);
#pragma unroll
        for (int mt = 0; mt < 2; mt++)
#pragma unroll
            for (int nt = 0; nt < 2; nt++) {
                float t0 = __shfl_xor_sync(0xffffffffu, cf[mt][nt][0], 1);
                float t1 = __shfl_xor_sync(0xffffffffu, cf[mt][nt][1], 1);
                float t2 = __shfl_xor_sync(0xffffffffu, cf[mt][nt][2], 1);
                float t3 = __shfl_xor_sync(0xffffffffu, cf[mt][nt][3], 1);
                const int c = n0 + wn * 16 + (lane & 3) * 2 + nt * 8;
                const int j = c >> 2;
                const int r = m0 + wm * 32 + (lane >> 2) + mt * 16;
                int b;
                float gi, gf, gg, go;
                if (!parity) { b = r;     gi = cf[mt][nt][0]; gf = cf[mt][nt][1]; gg = t0; go = t1; }
                else         { b = r + 8; gi = t2;            gf = t3;            gg = cf[mt][nt][2]; go = cf[mt][nt][3]; }
                const float4 bs = *(const float4*)&g_bias1r[4 * j];
                gi += bs.x;
                gf += bs.y;
                gg += bs.z;
                go += bs.w;
                const int idx = b * 256 + j;
                float cc = sig_precise(gf) * g_c1[idx] + sig_precise(gi) * tanhf(gg);
                float hh = sig_precise(go) * tanhf(cc);
                g_c1[idx] = cc;
                g_h1[idx] = hh;
                g_xcatfch[b * 512 + j] = __float2half(hh);
            }
    }
    grid_barrier(&eps);

    // ===== P2: fc1+relu+Wfc2 partial (ctas 0-31) | dec_proj (ctas 32-63) =====
    if (cta < 32) {
        __shared__ float sfc[64][4];
        const int m0 = (cta & 7) * 64, n0 = (cta >> 3) * 64;
        gemm_mma_db(g_xcatfch, 512, g_Wfc1h, 512, m0, n0, 512, cf);
        float s0[2] = {0.f, 0.f}, s1[2] = {0.f, 0.f};
#pragma unroll
        for (int mt = 0; mt < 2; mt++)
#pragma unroll
            for (int nt = 0; nt < 2; nt++) {
                const int c = n0 + wn * 16 + (lane & 3) * 2 + nt * 8;
                const float b0 = bfc1[c], b1 = bfc1[c + 1];
                const float w0 = Wfc2[c], w1 = Wfc2[c + 1];
                s0[mt] += fmaxf(cf[mt][nt][0] + b0, 0.f) * w0 + fmaxf(cf[mt][nt][1] + b1, 0.f) * w1;
                s1[mt] += fmaxf(cf[mt][nt][2] + b0, 0.f) * w0 + fmaxf(cf[mt][nt][3] + b1, 0.f) * w1;
            }
#pragma unroll
        for (int off = 1; off < 4; off <<= 1) {
#pragma unroll
            for (int mt = 0; mt < 2; mt++) {
                s0[mt] += __shfl_xor_sync(0xffffffffu, s0[mt], off);
                s1[mt] += __shfl_xor_sync(0xffffffffu, s1[mt], off);
            }
        }
        if ((lane & 3) == 0) {
#pragma unroll
            for (int mt = 0; mt < 2; mt++) {
                int rl = wm * 32 + (lane >> 2) + mt * 16;
                sfc[rl][wn] = s0[mt];
                sfc[rl + 8][wn] = s1[mt];
            }
        }
        __syncthreads();
        if (tid < 64) {
            float p = sfc[tid][0] + sfc[tid][1] + sfc[tid][2] + sfc[tid][3];
            g_fcp4[(m0 + tid) * 4 + (cta >> 3)] = p;
        }
    } else if (cta < 64) {
        const int c2 = cta - 32;
        const int m0 = (c2 & 7) * 64, n0 = (c2 >> 3) * 64;
        gemm_mma_db(g_xcatfch, 512, g_Wt_dech, 256, m0, n0, 256, cf);
        const int erow = wm * 32 + (lane >> 2);
        const int ecol = wn * 16 + (lane & 3) * 2;
#pragma unroll
        for (int mt = 0; mt < 2; mt++)
#pragma unroll
            for (int nt = 0; nt < 2; nt++) {
                int r = m0 + erow + mt * 16, c = n0 + ecol + nt * 8;
                *(float2*)&g_dp[(size_t)r * AA + c] = make_float2(cf[mt][nt][0], cf[mt][nt][1]);
                *(float2*)&g_dp[(size_t)(r + 8) * AA + c] = make_float2(cf[mt][nt][2], cf[mt][nt][3]);
            }
    }
}

// ---------------- finalize last step's fc output ----------------
__global__ void finalize(const float* __restrict__ bfc2, float* __restrict__ outs) {
    int b = blockIdx.x * 256 + threadIdx.x;
    const float4 p = *(const float4*)&g_fcp4[b * 4];
    outs[b * TPRED + (TPRED - 1)] = (p.x + p.y) + (p.z + p.w) + bfc2[0];
}

// ---------------- initial dec_proj from encoder_hidden[1] ----------------
__global__ __launch_bounds__(256) void dp_init(const float* __restrict__ Wad) {
    __shared__ float sA[8][256];
    const int b0 = blockIdx.x * 8;
    const int tid = threadIdx.x;
#pragma unroll
    for (int q = 0; q < 2; q++) {
        int f4 = q * 256 + tid;
        int r = f4 >> 6, c = (f4 & 63) * 4;
        *(float4*)&sA[r][c] = *(const float4*)&g_h1[(size_t)(b0 + r) * 256 + c];
    }
    __syncthreads();
    float dpa[8];
#pragma unroll
    for (int r = 0; r < 8; r++) dpa[r] = 0.f;
#pragma unroll 4
    for (int h = 0; h < 256; h++) {
        const float wv = Wad[(size_t)h * AA + tid];
#pragma unroll
        for (int r = 0; r < 8; r++) dpa[r] = fmaf(sA[r][h], wv, dpa[r]);
    }
#pragma unroll
    for (int r = 0; r < 8; r++) g_dp[(b0 + r) * 256 + tid] = dpa[r];
}

// ---------------- host launcher ----------------
extern "C" void kernel_launch(void* const* d_in, const int* in_sizes, int n_in,
                              void* d_out, int out_size) {
    int off = (in_sizes[0] == 1) ? 1 : 0;
    const float* enc_out = (const float*)d_in[off + 0];
    const float* enc_h = (const float*)d_in[off + 1];
    const float* enc_c = (const float*)d_in[off + 2];
    const float* Wae = (const float*)d_in[off + 3];
    const float* Wad = (const float*)d_in[off + 4];
    const float* v = (const float*)d_in[off + 5];
    const float* Wih0 = (const float*)d_in[off + 6];
    const float* Whh0 = (const float*)d_in[off + 7];
    const float* bih0 = (const float*)d_in[off + 8];
    const float* bhh0 = (const float*)d_in[off + 9];
    const float* Wih1 = (const float*)d_in[off + 10];
    const float* Whh1 = (const float*)d_in[off + 11];
    const float* bih1 = (const float*)d_in[off + 12];
    const float* bhh1 = (const float*)d_in[off + 13];
    const float* Wfc1 = (const float*)d_in[off + 14];
    const float* bfc1 = (const float*)d_in[off + 15];
    const float* Wfc2 = (const float*)d_in[off + 16];
    const float* bfc2 = (const float*)d_in[off + 17];

    float* out = (float*)d_out;
    float* attn_base = out + (size_t)BB * TPRED;

    init_state<<<(BB * HH + 255) / 256, 256>>>(enc_h, enc_c);
    prep<<<2048, 256>>>(Wae, Wad, Wih0, Whh0, bih0, bhh0, Wih1, Whh1, bih1, bhh1, Wfc1);
    prep_eo<<<(BB * THIST * HENC / 4) / 256, 256>>>(enc_out);
    encproj_mma<<<dim3(4, 4096), 256>>>();
    dp_init<<<BB / 8, 256>>>(Wad);

    for (int s = 0; s < TPRED; s++) {
        attn_step<<<BB, 256>>>(v, attn_base + (size_t)s * BB * THIST, bfc2, out, s);
        recurrent_step<<<NCTAS, 256>>>(bfc1, Wfc2);
    }
    finalize<<<2, 256>>>(bfc2, out);
    (void)n_in;
    (void)out_size;
}